// round 12
// baseline (speedup 1.0000x reference)
#include <cuda_runtime.h>
#include <cuda_fp16.h>
#include <cstdint>
#include <math.h>

#define M_    100
#define C_    30
#define D_    300
#define K_    3
#define MC    3000
#define MM    10000
#define KPAD2 160            // half2 per row (320 fp16, padded from 300)
#define K4    40             // float4 per row (640 B)
#define RPAD  3072           // padded MC rows
#define NPAD  320            // padded rows for R^T (e dim)
#define NCH   10             // chunks of 16 half2 (32 fp16 k-values)
#define LBPB  592            // persistent LBP blocks (4/SM, forced co-resident)

// ---------------- scratch ----------------
static __device__ float    d_f   [M_*D_];
static __device__ float    d_g   [M_*D_];
static __device__ float    d_psi [M_*C_];
static __device__ float    d_fD  [K_*M_*D_];
static __device__ float    d_s   [K_*M_*M_];
static __device__ float    d_a   [M_*M_*K_];
static __device__ float    d_Bt  [D_*D_];          // B^T (fp32 exact)
static __device__ uint32_t d_Apad[RPAD*KPAD2];     // ent, fp16x2, padded
static __device__ uint32_t d_Bpad[K_*RPAD*KPAD2];  // ER_k, fp16x2
static __device__ uint32_t d_Rt  [K_*NPAD*KPAD2];  // R_k^T, fp16x2
static __device__ __half   d_phi [MM*C_*C_];       // 18 MB, fp16, [i][j][p][q]
static __device__ float    d_mbarA[M_*M_*C_];
static __device__ float    d_mbarB[M_*M_*C_];
static __device__ float    d_S   [3][M_*C_];       // rotating stot buffers
static __device__ int      d_bar;                  // grid barrier counter

// ---------------- helpers ----------------
__device__ __forceinline__ uint32_t smem_u32(const void* p) {
    uint32_t a;
    asm("{ .reg .u64 t; cvta.to.shared.u64 t, %1; cvt.u32.u64 %0, t; }" : "=r"(a) : "l"(p));
    return a;
}
__device__ __forceinline__ void cpasync16(uint32_t dst, const void* src) {
    asm volatile("{\n\t.reg .u64 g;\n\tcvta.to.global.u64 g, %1;\n\t"
                 "cp.async.cg.shared.global [%0], [g], 16;\n\t}"
                 :: "r"(dst), "l"(src));
}
__device__ __forceinline__ void cpasync16z(uint32_t dst, const void* src, int bytes) {
    asm volatile("{\n\t.reg .u64 g;\n\tcvta.to.global.u64 g, %1;\n\t"
                 "cp.async.cg.shared.global [%0], [g], 16, %2;\n\t}"
                 :: "r"(dst), "l"(src), "r"(bytes));
}
__device__ __forceinline__ void cpasync4z(uint32_t dst, const void* src, int bytes) {
    asm volatile("{\n\t.reg .u64 g;\n\tcvta.to.global.u64 g, %1;\n\t"
                 "cp.async.ca.shared.global [%0], [g], 4, %2;\n\t}"
                 :: "r"(dst), "l"(src), "r"(bytes));
}
#define CP_COMMIT() asm volatile("cp.async.commit_group;" ::: "memory")
#define CP_WAIT(n)  asm volatile("cp.async.wait_group %0;" :: "n"(n) : "memory")

__device__ __forceinline__ void mma_f16(float* c, const uint32_t* a, const uint32_t* b) {
    asm volatile("mma.sync.aligned.m16n8k16.row.col.f32.f16.f16.f32 "
        "{%0,%1,%2,%3}, {%4,%5,%6,%7}, {%8,%9}, {%0,%1,%2,%3};"
        : "+f"(c[0]), "+f"(c[1]), "+f"(c[2]), "+f"(c[3])
        : "r"(a[0]), "r"(a[1]), "r"(a[2]), "r"(a[3]), "r"(b[0]), "r"(b[1]));
}

// ---------------- pack_front: zeros + Bt + barrier reset (side stream) ------
__global__ void pack_front(const float* __restrict__ Bm) {
    int idx = blockIdx.x * blockDim.x + threadIdx.x;
    int stride = gridDim.x * blockDim.x;
    if (idx == 0) d_bar = 0;
    for (int i = idx; i < M_*D_; i += stride) { d_f[i] = 0.f; d_g[i] = 0.f; }
    for (int i = idx; i < K_*M_*D_; i += stride) d_fD[i] = 0.f;
    for (int i = idx; i < K_*MM; i += stride) d_s[i] = 0.f;
    for (int i = idx; i < M_*M_*C_; i += stride) d_mbarA[i] = 0.f;
    for (int i = idx; i < M_*C_; i += stride) { d_S[0][i] = 0.f; d_S[1][i] = 0.f; }
    for (int i = idx; i < D_*D_; i += stride) {
        int dd = i / D_, e = i - dd * D_;
        d_Bt[i] = Bm[e * D_ + dd];
    }
}
// ---------------- pack_er: fp16 Apad + Rt (main stream) ---------------------
__global__ void pack_er(const float* __restrict__ ent, const float* __restrict__ R) {
    int idx = blockIdx.x * blockDim.x + threadIdx.x;
    int stride = gridDim.x * blockDim.x;
    for (int i = idx; i < RPAD*KPAD2; i += stride) {
        int r = i / KPAD2, c2 = i - r * KPAD2;
        int d0 = c2 * 2;
        float x = (r < MC && d0     < D_) ? ent[r * D_ + d0]     : 0.f;
        float y = (r < MC && d0 + 1 < D_) ? ent[r * D_ + d0 + 1] : 0.f;
        half2 h = __floats2half2_rn(x, y);
        d_Apad[i] = *reinterpret_cast<uint32_t*>(&h);
    }
    for (int i = idx; i < K_*NPAD*KPAD2; i += stride) {
        int k = i / (NPAD * KPAD2);
        int rem = i - k * (NPAD * KPAD2);
        int n = rem / KPAD2, c2 = rem - n * KPAD2;
        int d0 = c2 * 2;
        float x = (n < D_ && d0     < D_) ? R[k * D_ * D_ + d0       * D_ + n] : 0.f;
        float y = (n < D_ && d0 + 1 < D_) ? R[k * D_ * D_ + (d0 + 1) * D_ + n] : 0.f;
        half2 h = __floats2half2_rn(x, y);
        d_Rt[i] = *reinterpret_cast<uint32_t*>(&h);
    }
}

// ================= ER via mma.sync fp16 (unchanged) ====================
#define ER_BUF 3840
__global__ void __launch_bounds__(256) er_mma() {
    extern __shared__ uint32_t sm[];
    const int tid = threadIdx.x, lane = tid & 31, wid = tid >> 5;
    const int warpM = wid & 3, warpN = wid >> 2;
    const int row0 = blockIdx.y * 128;
    const int n0   = blockIdx.x * 64;
    const uint32_t smb = smem_u32(sm);
    const float4* Ag = (const float4*)(d_Apad + (size_t)row0 * KPAD2);
    const float4* Bg = (const float4*)(d_Rt + (size_t)blockIdx.z * NPAD * KPAD2
                                       + (size_t)n0 * KPAD2);
    float acc[2][4][4] = {};

    auto prefetch = [&](int ch, int buf) {
        int c4o = ch * 4;
        uint32_t base = smb + buf * ER_BUF * 4;
        #pragma unroll
        for (int it = 0; it < 2; it++) {
            int idx = tid + it * 256;
            int m = idx >> 2, q = idx & 3;
            cpasync16(base + (m * 20 + q * 4) * 4, Ag + m * K4 + c4o + q);
        }
        {
            int n = tid >> 2, q = tid & 3;
            cpasync16(base + (2560 + n * 20 + q * 4) * 4, Bg + n * K4 + c4o + q);
        }
    };

    prefetch(0, 0);
    CP_COMMIT();
    for (int ch = 0; ch < NCH; ch++) {
        if (ch + 1 < NCH) { prefetch(ch + 1, (ch + 1) & 1); CP_COMMIT(); CP_WAIT(1); }
        else CP_WAIT(0);
        __syncthreads();
        const uint32_t* As = sm + (ch & 1) * ER_BUF;
        const uint32_t* Bs = As + 2560;
        #pragma unroll
        for (int ks = 0; ks < 2; ks++) {
            uint32_t af[2][4];
            #pragma unroll
            for (int mf = 0; mf < 2; mf++) {
                int r = warpM * 32 + mf * 16 + (lane >> 2);
                int c = ks * 8 + (lane & 3);
                af[mf][0] = As[r * 20 + c];
                af[mf][1] = As[(r + 8) * 20 + c];
                af[mf][2] = As[r * 20 + c + 4];
                af[mf][3] = As[(r + 8) * 20 + c + 4];
            }
            uint32_t bf[4][2];
            #pragma unroll
            for (int nf = 0; nf < 4; nf++) {
                int n = warpN * 32 + nf * 8 + (lane >> 2);
                int kk = ks * 8 + (lane & 3);
                bf[nf][0] = Bs[n * 20 + kk];
                bf[nf][1] = Bs[n * 20 + kk + 4];
            }
            #pragma unroll
            for (int mf = 0; mf < 2; mf++)
                #pragma unroll
                for (int nf = 0; nf < 4; nf++)
                    mma_f16(acc[mf][nf], af[mf], bf[nf]);
        }
        __syncthreads();
    }

    uint32_t* Bout = d_Bpad + (size_t)blockIdx.z * RPAD * KPAD2;
    #pragma unroll
    for (int mf = 0; mf < 2; mf++) {
        int r = row0 + warpM * 32 + mf * 16 + (lane >> 2);
        #pragma unroll
        for (int nf = 0; nf < 4; nf++) {
            int c = n0 + warpN * 32 + nf * 8 + (lane & 3) * 2;
            half2 h0 = __floats2half2_rn(acc[mf][nf][0], acc[mf][nf][1]);
            half2 h1 = __floats2half2_rn(acc[mf][nf][2], acc[mf][nf][3]);
            Bout[(size_t)r * KPAD2 + (c >> 1)]       = *reinterpret_cast<uint32_t*>(&h0);
            Bout[(size_t)(r + 8) * KPAD2 + (c >> 1)] = *reinterpret_cast<uint32_t*>(&h1);
        }
    }
}

// ===== phi via mma.sync fp16, 3 fused kinds; OUT = fp16 [i][j][p][q] ========
#define PHI_BUF 6400
__global__ void __launch_bounds__(256) phi_mma() {
    extern __shared__ uint32_t sm[];
    const int tid = threadIdx.x, lane = tid & 31, wid = tid >> 5;
    const int warpM = wid & 3, warpN = wid >> 2;
    const int row0 = blockIdx.y * 128;
    const int col0 = blockIdx.x * 64;
    const uint32_t smb = smem_u32(sm);
    const float4* Ag = (const float4*)(d_Apad + (size_t)row0 * KPAD2);
    float acc[3][2][4][4] = {};

    auto prefetch = [&](int ch, int buf) {
        int c4o = ch * 4;
        uint32_t base = smb + buf * PHI_BUF * 4;
        #pragma unroll
        for (int it = 0; it < 2; it++) {
            int idx = tid + it * 256;
            int m = idx >> 2, q = idx & 3;
            cpasync16(base + (m * 20 + q * 4) * 4, Ag + m * K4 + c4o + q);
        }
        #pragma unroll
        for (int it = 0; it < 3; it++) {
            int idx = tid + it * 256;
            int kb = idx >> 8, rem = idx & 255;
            int n = rem >> 2, q = rem & 3;
            const float4* Bg = (const float4*)(d_Bpad + (size_t)kb * RPAD * KPAD2
                                               + (size_t)col0 * KPAD2);
            cpasync16(base + (2560 + kb * 1280 + n * 20 + q * 4) * 4,
                      Bg + n * K4 + c4o + q);
        }
    };

    prefetch(0, 0);
    CP_COMMIT();
    for (int ch = 0; ch < NCH; ch++) {
        if (ch + 1 < NCH) { prefetch(ch + 1, (ch + 1) & 1); CP_COMMIT(); CP_WAIT(1); }
        else CP_WAIT(0);
        __syncthreads();
        const uint32_t* As = sm + (ch & 1) * PHI_BUF;
        #pragma unroll
        for (int ks = 0; ks < 2; ks++) {
            uint32_t af[2][4];
            #pragma unroll
            for (int mf = 0; mf < 2; mf++) {
                int r = warpM * 32 + mf * 16 + (lane >> 2);
                int c = ks * 8 + (lane & 3);
                af[mf][0] = As[r * 20 + c];
                af[mf][1] = As[(r + 8) * 20 + c];
                af[mf][2] = As[r * 20 + c + 4];
                af[mf][3] = As[(r + 8) * 20 + c + 4];
            }
            #pragma unroll
            for (int kb = 0; kb < 3; kb++) {
                const uint32_t* Bs = As + 2560 + kb * 1280;
                uint32_t bf[4][2];
                #pragma unroll
                for (int nf = 0; nf < 4; nf++) {
                    int n = warpN * 32 + nf * 8 + (lane >> 2);
                    int kk = ks * 8 + (lane & 3);
                    bf[nf][0] = Bs[n * 20 + kk];
                    bf[nf][1] = Bs[n * 20 + kk + 4];
                }
                #pragma unroll
                for (int mf = 0; mf < 2; mf++)
                    #pragma unroll
                    for (int nf = 0; nf < 4; nf++)
                        mma_f16(acc[kb][mf][nf], af[mf], bf[nf]);
            }
        }
        __syncthreads();
    }

    #pragma unroll
    for (int mf = 0; mf < 2; mf++) {
        #pragma unroll
        for (int half = 0; half < 2; half++) {
            int r = row0 + warpM * 32 + mf * 16 + (lane >> 2) + half * 8;
            if (r >= MC) continue;
            int i = r / C_, p = r % C_;
            #pragma unroll
            for (int nf = 0; nf < 4; nf++) {
                int c = col0 + warpN * 32 + nf * 8 + (lane & 3) * 2;
                if (c >= MC) continue;
                int j = c / C_, q = c % C_;
                const float* aw = d_a + (i * M_ + j) * 3;
                float w0 = aw[0], w1 = aw[1], w2 = aw[2];
                int e0 = half * 2;
                float v0 = acc[0][mf][nf][e0]     * w0 + acc[1][mf][nf][e0]     * w1
                         + acc[2][mf][nf][e0]     * w2;
                float v1 = acc[0][mf][nf][e0 + 1] * w0 + acc[1][mf][nf][e0 + 1] * w1
                         + acc[2][mf][nf][e0 + 1] * w2;
                half2 hv = __floats2half2_rn(v0, v1);
                *reinterpret_cast<uint32_t*>(
                    d_phi + ((size_t)(i * M_ + j) * (C_ * C_)) + p * C_ + q)
                    = *reinterpret_cast<uint32_t*>(&hv);
            }
        }
    }
}

// ============ cp.async double-buffered split-K fp32 GEMMs (unchanged) =======
__global__ void __launch_bounds__(256) gemm_nn_ca(
    const float* __restrict__ A, const float* __restrict__ B0,
    const float* __restrict__ B1, float* __restrict__ C0, float* __restrict__ C1,
    int M, int N, int K, int KC, int KS, long sB, long sC)
{
    __shared__ float As[2][64][20];
    __shared__ float Bs[2][16][64];
    const int batch = blockIdx.z / KS, kz = blockIdx.z % KS;
    const float* Bp = (batch == 0) ? B0 : B1 + (long)(batch - 1) * sB;
    float*       Cp = (batch == 0) ? C0 : C1 + (long)(batch - 1) * sC;
    const int tid = threadIdx.x;
    const int row0 = blockIdx.y * 64, col0 = blockIdx.x * 64;
    const int tm = (tid >> 4) * 4, tn = (tid & 15) * 4;
    const int k0 = kz * KC, kend = min(K, k0 + KC);
    if (k0 >= K) return;
    const int S = (kend - k0 + 15) >> 4;
    float acc[4][4] = {};

    auto prefetch = [&](int s, int buf) {
        int kb = k0 + s * 16;
        {
            int m = tid >> 2, q = tid & 3;
            int gr = row0 + m, gc = kb + q * 4;
            int bytes = (gr < M && gc < kend) ? min(16, (kend - gc) * 4) : 0;
            cpasync16z(smem_u32(&As[buf][m][q * 4]), A + (long)gr * K + gc, bytes);
        }
        {
            int kk = tid >> 4, q = tid & 15;
            int gr = kb + kk, gc = col0 + q * 4;
            int bytes = (gr < kend && gc < N) ? min(16, (N - gc) * 4) : 0;
            cpasync16z(smem_u32(&Bs[buf][kk][q * 4]), Bp + (long)gr * N + gc, bytes);
        }
    };

    prefetch(0, 0);
    CP_COMMIT();
    for (int s = 0; s < S; s++) {
        if (s + 1 < S) { prefetch(s + 1, (s + 1) & 1); CP_COMMIT(); CP_WAIT(1); }
        else CP_WAIT(0);
        __syncthreads();
        int buf = s & 1;
        #pragma unroll
        for (int kk = 0; kk < 16; kk++) {
            float a4[4], b4[4];
            #pragma unroll
            for (int x = 0; x < 4; x++) a4[x] = As[buf][tm + x][kk];
            #pragma unroll
            for (int y = 0; y < 4; y++) b4[y] = Bs[buf][kk][tn + y];
            #pragma unroll
            for (int x = 0; x < 4; x++)
                #pragma unroll
                for (int y = 0; y < 4; y++) acc[x][y] += a4[x] * b4[y];
        }
        __syncthreads();
    }
    #pragma unroll
    for (int x = 0; x < 4; x++) {
        int rr = row0 + tm + x;
        if (rr >= M) continue;
        #pragma unroll
        for (int y = 0; y < 4; y++) {
            int cc = col0 + tn + y;
            if (cc >= N) continue;
            atomicAdd(&Cp[(long)rr * N + cc], acc[x][y]);
        }
    }
}

__global__ void __launch_bounds__(256) gemm_nt_ca(
    const float* __restrict__ A, const float* __restrict__ B, float* __restrict__ C,
    int M, int N, int K, int KC, int KS, long sA, long sC)
{
    __shared__ float As[2][64][20];
    __shared__ float Bs[2][16][68];
    const int batch = blockIdx.z / KS, kz = blockIdx.z % KS;
    const float* Ap = A + (long)batch * sA;
    float*       Cp = C + (long)batch * sC;
    const int tid = threadIdx.x;
    const int row0 = blockIdx.y * 64, col0 = blockIdx.x * 64;
    const int tm = (tid >> 4) * 4, tn = (tid & 15) * 4;
    const int k0 = kz * KC, kend = min(K, k0 + KC);
    if (k0 >= K) return;
    const int S = (kend - k0 + 15) >> 4;
    float acc[4][4] = {};

    auto prefetch = [&](int s, int buf) {
        int kb = k0 + s * 16;
        {
            int m = tid >> 2, q = tid & 3;
            int gr = row0 + m, gc = kb + q * 4;
            int bytes = (gr < M && gc < kend) ? min(16, (kend - gc) * 4) : 0;
            cpasync16z(smem_u32(&As[buf][m][q * 4]), Ap + (long)gr * K + gc, bytes);
        }
        #pragma unroll
        for (int it = 0; it < 4; it++) {
            int idx = tid + it * 256;
            int n = idx >> 4, kk = idx & 15;
            int gr = col0 + n, gc = kb + kk;
            int bytes = (gr < N && gc < kend) ? 4 : 0;
            cpasync4z(smem_u32(&Bs[buf][kk][n]), B + (long)gr * K + gc, bytes);
        }
    };

    prefetch(0, 0);
    CP_COMMIT();
    for (int s = 0; s < S; s++) {
        if (s + 1 < S) { prefetch(s + 1, (s + 1) & 1); CP_COMMIT(); CP_WAIT(1); }
        else CP_WAIT(0);
        __syncthreads();
        int buf = s & 1;
        #pragma unroll
        for (int kk = 0; kk < 16; kk++) {
            float a4[4], b4[4];
            #pragma unroll
            for (int x = 0; x < 4; x++) a4[x] = As[buf][tm + x][kk];
            #pragma unroll
            for (int y = 0; y < 4; y++) b4[y] = Bs[buf][kk][tn + y];
            #pragma unroll
            for (int x = 0; x < 4; x++)
                #pragma unroll
                for (int y = 0; y < 4; y++) acc[x][y] += a4[x] * b4[y];
        }
        __syncthreads();
    }
    #pragma unroll
    for (int x = 0; x < 4; x++) {
        int rr = row0 + tm + x;
        if (rr >= M) continue;
        #pragma unroll
        for (int y = 0; y < 4; y++) {
            int cc = col0 + tn + y;
            if (cc >= N) continue;
            atomicAdd(&Cp[(long)rr * N + cc], acc[x][y]);
        }
    }
}

__global__ void ftanh(const float* __restrict__ bias) {
    int idx = blockIdx.x * blockDim.x + threadIdx.x;
    if (idx >= M_ * D_) return;
    d_f[idx] = tanhf(d_f[idx] + bias[idx % D_]);
}

// ---------------- a softmax (needed by phi) ----------------
__global__ void a_kernel()
{
    int ij = blockIdx.x * blockDim.x + threadIdx.x;
    if (ij >= MM) return;
    const float scale = 0.05773502691896258f;
    float s0 = d_s[0 * MM + ij] * scale;
    float s1 = d_s[1 * MM + ij] * scale;
    float s2 = d_s[2 * MM + ij] * scale;
    float mx = fmaxf(s0, fmaxf(s1, s2));
    float e0 = expf(s0 - mx), e1 = expf(s1 - mx), e2 = expf(s2 - mx);
    float inv = 1.f / (e0 + e1 + e2);
    d_a[ij * 3 + 0] = e0 * inv;
    d_a[ij * 3 + 1] = e1 * inv;
    d_a[ij * 3 + 2] = e2 * inv;
}

// ---------------- psi (needed only by LBP; overlaps phi) ----------------
__global__ void psi_kernel(const float* __restrict__ ent)
{
    int m = blockIdx.x;
    __shared__ float gs[D_];
    for (int d = threadIdx.x; d < D_; d += blockDim.x) gs[d] = d_g[m * D_ + d];
    __syncthreads();
    int w = threadIdx.x >> 5, lane = threadIdx.x & 31;
    for (int c = w; c < C_; c += (blockDim.x >> 5)) {
        const float* e = ent + ((long)m * C_ + c) * D_;
        float s = 0.f;
        for (int d = lane; d < D_; d += 32) s += e[d] * gs[d];
        #pragma unroll
        for (int o = 16; o; o >>= 1) s += __shfl_down_sync(0xffffffffu, s, o);
        if (lane == 0) d_psi[m * C_ + c] = s;
    }
}

// ---------------- persistent LBP: 10 iterations + final, one launch ---------
// 592 blocks x 320 thr, FORCED 4 blocks/SM co-residency via launch_bounds.
// Cross-iteration global reads (mbar/stot) use __ldcv; phi/psi stay L1-cached
// (same (i,j) units every iteration -> phi slice becomes L1-resident).
__global__ void __launch_bounds__(320, 4) lbp_persist(float* __restrict__ out)
{
    const int tid = threadIdx.x;
    const int w = tid >> 5, lane = tid & 31;
    const int b = blockIdx.x;
    __shared__ float tt[10][32];
    __shared__ float sred[10][32];

    for (int it = 0; it < 10; it++) {
        const float* msrc = (it & 1) ? d_mbarB : d_mbarA;
        float*       mdst = (it & 1) ? d_mbarA : d_mbarB;
        const float* ssrc = d_S[it % 3];
        float*       sdst = d_S[(it + 1) % 3];
        float*       szero = d_S[(it + 2) % 3];

        if (b < 12) {
            int z = b * 320 + tid;
            if (z < M_ * C_) szero[z] = 0.f;
        }

        for (int unit = b; unit < 1000; unit += LBPB) {
            const int j = unit % M_;
            const int i = (unit / M_) * 10 + w;

            if (lane < C_)
                tt[w][lane] = d_psi[i * C_ + lane] + __ldcv(&ssrc[i * C_ + lane])
                            - __ldcv(&msrc[(j * M_ + i) * C_ + lane]);
            __syncwarp();

            const __half* ph = d_phi + (size_t)(i * M_ + j) * (C_ * C_);
            float mv = -1e30f;
            if (lane < C_) {
                #pragma unroll 6
                for (int p = 0; p < C_; p++)
                    mv = fmaxf(mv, tt[w][p] + __half2float(ph[p * C_ + lane]));
                mv = fmaxf(mv, 0.f);
            }
            float mx = (lane < C_) ? mv : -1e30f;
            #pragma unroll
            for (int o = 16; o; o >>= 1) mx = fmaxf(mx, __shfl_xor_sync(0xffffffffu, mx, o));
            float e = (lane < C_) ? __expf(mv - mx) : 0.f;
            float sum = e;
            #pragma unroll
            for (int o = 16; o; o >>= 1) sum += __shfl_xor_sync(0xffffffffu, sum, o);

            float newm = 0.f;
            if (lane < C_) {
                float sm = e / sum;
                float old = __ldcv(&msrc[(i * M_ + j) * C_ + lane]);
                newm = __logf(0.5f * __expf(old) + 0.5f * sm);
                mdst[(i * M_ + j) * C_ + lane] = newm;
            }
            sred[w][lane] = newm;
            __syncthreads();

            if (tid < C_) {
                float s = 0.f;
                #pragma unroll
                for (int w2 = 0; w2 < 10; w2++) s += sred[w2][tid];
                atomicAdd(&sdst[j * C_ + tid], s);
            }
            __syncthreads();
        }

        // grid barrier (sense via monotonically increasing target)
        __threadfence();
        __syncthreads();
        if (tid == 0) {
            atomicAdd(&d_bar, 1);
            int target = LBPB * (it + 1);
            while (*(volatile int*)&d_bar < target) __nanosleep(64);
        }
        __syncthreads();
    }

    // final: out[i,:] = softmax_q(psi + stot - mbar[i,i,:]); mbar=A, stot=S[1]
    if (b < M_ && tid < 32) {
        int i = b;
        float u = -1e30f;
        if (lane < C_)
            u = d_psi[i * C_ + lane] + __ldcv(&d_S[1][i * C_ + lane])
              - __ldcv(&d_mbarA[(i * M_ + i) * C_ + lane]);
        float mx = u;
        #pragma unroll
        for (int o = 16; o; o >>= 1) mx = fmaxf(mx, __shfl_xor_sync(0xffffffffu, mx, o));
        float e = (lane < C_) ? expf(u - mx) : 0.f;
        float sum = e;
        #pragma unroll
        for (int o = 16; o; o >>= 1) sum += __shfl_xor_sync(0xffffffffu, sum, o);
        if (lane < C_) out[i * C_ + lane] = e / sum;
    }
}

// ---------------- host ----------------
extern "C" void kernel_launch(void* const* d_in, const int* in_sizes, int n_in,
                              void* d_out, int out_size)
{
    const float* ent    = (const float*)d_in[0];
    const float* fmc_in = (const float*)d_in[1];
    const float* W_fmc  = (const float*)d_in[2];
    const float* b_fmc  = (const float*)d_in[3];
    const float* Bmat   = (const float*)d_in[4];
    const float* Rmat   = (const float*)d_in[5];
    const float* Dmat   = (const float*)d_in[6];
    float* out = (float*)d_out;

    float *pf, *pg, *pfD, *ps, *pBt;
    cudaGetSymbolAddress((void**)&pf,  d_f);
    cudaGetSymbolAddress((void**)&pg,  d_g);
    cudaGetSymbolAddress((void**)&pfD, d_fD);
    cudaGetSymbolAddress((void**)&ps,  d_s);
    cudaGetSymbolAddress((void**)&pBt, d_Bt);

    // one-time stream/event setup (first call = correctness run, not capture)
    static cudaStream_t s_side = nullptr;
    static cudaEvent_t ev_fork = nullptr, ev_join = nullptr, ev_psi = nullptr;
    if (s_side == nullptr) {
        cudaStreamCreateWithFlags(&s_side, cudaStreamNonBlocking);
        cudaEventCreateWithFlags(&ev_fork, cudaEventDisableTiming);
        cudaEventCreateWithFlags(&ev_join, cudaEventDisableTiming);
        cudaEventCreateWithFlags(&ev_psi,  cudaEventDisableTiming);
        cudaFuncSetAttribute(er_mma,  cudaFuncAttributeMaxDynamicSharedMemorySize, 2 * ER_BUF * 4);
        cudaFuncSetAttribute(phi_mma, cudaFuncAttributeMaxDynamicSharedMemorySize, 2 * PHI_BUF * 4);
    }
    const cudaStream_t mainS = cudaStreamPerThread;

    // fork: side stream runs the front chain concurrently with pack_er + er_mma
    cudaEventRecord(ev_fork, mainS);
    cudaStreamWaitEvent(s_side, ev_fork, 0);

    // ---- side stream: zeros/Bt + f -> tanh -> g+fD -> s -> a ; then psi ----
    pack_front<<<256, 256, 0, s_side>>>(Bmat);
    gemm_nn_ca<<<dim3(5, 2, 15), 256, 0, s_side>>>(fmc_in, W_fmc, nullptr, pf, nullptr,
                                                   100, 300, 900, 64, 15, 0, 0);
    ftanh<<<(M_ * D_ + 255) / 256, 256, 0, s_side>>>(b_fmc);
    gemm_nn_ca<<<dim3(5, 2, 20), 256, 0, s_side>>>(pf, pBt, Dmat, pg, pfD,
                                                   100, 300, 300, 64, 5, 90000, 30000);
    gemm_nt_ca<<<dim3(2, 2, 15), 256, 0, s_side>>>(pfD, pf, ps, 100, 100, 300, 64, 5,
                                                   30000, 10000);
    a_kernel<<<40, 256, 0, s_side>>>();
    cudaEventRecord(ev_join, s_side);            // phi needs only d_a from here
    psi_kernel<<<100, 256, 0, s_side>>>(ent);    // overlaps phi_mma
    cudaEventRecord(ev_psi, s_side);

    // ---- main stream: pack_er -> er_mma ----
    pack_er<<<256, 256, 0, mainS>>>(ent, Rmat);
    er_mma<<<dim3(5, 24, 3), 256, 2 * ER_BUF * 4, mainS>>>();

    // join: phi needs d_a (side) + d_Bpad (main)
    cudaStreamWaitEvent(mainS, ev_join, 0);
    phi_mma<<<dim3(47, 24), 256, 2 * PHI_BUF * 4, mainS>>>();

    // persistent LBP (needs psi + phi); includes final softmax
    cudaStreamWaitEvent(mainS, ev_psi, 0);
    lbp_persist<<<LBPB, 320, 0, mainS>>>(out);
}

// round 14
// speedup vs baseline: 1.0859x; 1.0859x over previous
#include <cuda_runtime.h>
#include <cuda_fp16.h>
#include <cstdint>
#include <math.h>

#define M_    100
#define C_    30
#define D_    300
#define K_    3
#define MC    3000
#define MM    10000
#define KPAD2 160            // half2 per row (320 fp16, padded from 300)
#define K4    40             // float4 per row (640 B)
#define RPAD  3072           // padded MC rows
#define NPAD  320            // padded rows for R^T (e dim)
#define NCH   10             // chunks of 16 half2 (32 fp16 k-values)

// ---------------- scratch ----------------
static __device__ float    d_f   [M_*D_];
static __device__ float    d_g   [M_*D_];
static __device__ float    d_psi [M_*C_];
static __device__ float    d_fD  [K_*M_*D_];
static __device__ float    d_s   [K_*M_*M_];
static __device__ float    d_a   [M_*M_*K_];
static __device__ float    d_Bt  [D_*D_];          // B^T (fp32 exact)
static __device__ uint32_t d_Apad[RPAD*KPAD2];     // ent, fp16x2, padded
static __device__ uint32_t d_Bpad[K_*RPAD*KPAD2];  // ER_k, fp16x2
static __device__ uint32_t d_Rt  [K_*NPAD*KPAD2];  // R_k^T, fp16x2
static __device__ __half   d_phi [MM*C_*C_];       // 18 MB, fp16, [i][j][p][q]
static __device__ float    d_mbarA[M_*M_*C_];
static __device__ float    d_mbarB[M_*M_*C_];
static __device__ float    d_S   [3][M_*C_];       // rotating stot buffers

// ---------------- helpers ----------------
__device__ __forceinline__ uint32_t smem_u32(const void* p) {
    uint32_t a;
    asm("{ .reg .u64 t; cvta.to.shared.u64 t, %1; cvt.u32.u64 %0, t; }" : "=r"(a) : "l"(p));
    return a;
}
__device__ __forceinline__ void cpasync16(uint32_t dst, const void* src) {
    asm volatile("{\n\t.reg .u64 g;\n\tcvta.to.global.u64 g, %1;\n\t"
                 "cp.async.cg.shared.global [%0], [g], 16;\n\t}"
                 :: "r"(dst), "l"(src));
}
__device__ __forceinline__ void cpasync16z(uint32_t dst, const void* src, int bytes) {
    asm volatile("{\n\t.reg .u64 g;\n\tcvta.to.global.u64 g, %1;\n\t"
                 "cp.async.cg.shared.global [%0], [g], 16, %2;\n\t}"
                 :: "r"(dst), "l"(src), "r"(bytes));
}
__device__ __forceinline__ void cpasync4z(uint32_t dst, const void* src, int bytes) {
    asm volatile("{\n\t.reg .u64 g;\n\tcvta.to.global.u64 g, %1;\n\t"
                 "cp.async.ca.shared.global [%0], [g], 4, %2;\n\t}"
                 :: "r"(dst), "l"(src), "r"(bytes));
}
#define CP_COMMIT() asm volatile("cp.async.commit_group;" ::: "memory")
#define CP_WAIT(n)  asm volatile("cp.async.wait_group %0;" :: "n"(n) : "memory")

__device__ __forceinline__ void mma_f16(float* c, const uint32_t* a, const uint32_t* b) {
    asm volatile("mma.sync.aligned.m16n8k16.row.col.f32.f16.f16.f32 "
        "{%0,%1,%2,%3}, {%4,%5,%6,%7}, {%8,%9}, {%0,%1,%2,%3};"
        : "+f"(c[0]), "+f"(c[1]), "+f"(c[2]), "+f"(c[3])
        : "r"(a[0]), "r"(a[1]), "r"(a[2]), "r"(a[3]), "r"(b[0]), "r"(b[1]));
}

// ---------------- pack_front: zeros + Bt (side stream) ----------------------
__global__ void pack_front(const float* __restrict__ Bm) {
    int idx = blockIdx.x * blockDim.x + threadIdx.x;
    int stride = gridDim.x * blockDim.x;
    for (int i = idx; i < M_*D_; i += stride) { d_f[i] = 0.f; d_g[i] = 0.f; }
    for (int i = idx; i < K_*M_*D_; i += stride) d_fD[i] = 0.f;
    for (int i = idx; i < K_*MM; i += stride) d_s[i] = 0.f;
    for (int i = idx; i < M_*M_*C_; i += stride) d_mbarA[i] = 0.f;
    for (int i = idx; i < M_*C_; i += stride) { d_S[0][i] = 0.f; d_S[1][i] = 0.f; }
    for (int i = idx; i < D_*D_; i += stride) {
        int dd = i / D_, e = i - dd * D_;
        d_Bt[i] = Bm[e * D_ + dd];
    }
}
// ---------------- pack_er: fp16 Apad + Rt (main stream) ---------------------
__global__ void pack_er(const float* __restrict__ ent, const float* __restrict__ R) {
    int idx = blockIdx.x * blockDim.x + threadIdx.x;
    int stride = gridDim.x * blockDim.x;
    for (int i = idx; i < RPAD*KPAD2; i += stride) {
        int r = i / KPAD2, c2 = i - r * KPAD2;
        int d0 = c2 * 2;
        float x = (r < MC && d0     < D_) ? ent[r * D_ + d0]     : 0.f;
        float y = (r < MC && d0 + 1 < D_) ? ent[r * D_ + d0 + 1] : 0.f;
        half2 h = __floats2half2_rn(x, y);
        d_Apad[i] = *reinterpret_cast<uint32_t*>(&h);
    }
    for (int i = idx; i < K_*NPAD*KPAD2; i += stride) {
        int k = i / (NPAD * KPAD2);
        int rem = i - k * (NPAD * KPAD2);
        int n = rem / KPAD2, c2 = rem - n * KPAD2;
        int d0 = c2 * 2;
        float x = (n < D_ && d0     < D_) ? R[k * D_ * D_ + d0       * D_ + n] : 0.f;
        float y = (n < D_ && d0 + 1 < D_) ? R[k * D_ * D_ + (d0 + 1) * D_ + n] : 0.f;
        half2 h = __floats2half2_rn(x, y);
        d_Rt[i] = *reinterpret_cast<uint32_t*>(&h);
    }
}

// ================= ER via mma.sync fp16 (unchanged) ====================
#define ER_BUF 3840
__global__ void __launch_bounds__(256) er_mma() {
    extern __shared__ uint32_t sm[];
    const int tid = threadIdx.x, lane = tid & 31, wid = tid >> 5;
    const int warpM = wid & 3, warpN = wid >> 2;
    const int row0 = blockIdx.y * 128;
    const int n0   = blockIdx.x * 64;
    const uint32_t smb = smem_u32(sm);
    const float4* Ag = (const float4*)(d_Apad + (size_t)row0 * KPAD2);
    const float4* Bg = (const float4*)(d_Rt + (size_t)blockIdx.z * NPAD * KPAD2
                                       + (size_t)n0 * KPAD2);
    float acc[2][4][4] = {};

    auto prefetch = [&](int ch, int buf) {
        int c4o = ch * 4;
        uint32_t base = smb + buf * ER_BUF * 4;
        #pragma unroll
        for (int it = 0; it < 2; it++) {
            int idx = tid + it * 256;
            int m = idx >> 2, q = idx & 3;
            cpasync16(base + (m * 20 + q * 4) * 4, Ag + m * K4 + c4o + q);
        }
        {
            int n = tid >> 2, q = tid & 3;
            cpasync16(base + (2560 + n * 20 + q * 4) * 4, Bg + n * K4 + c4o + q);
        }
    };

    prefetch(0, 0);
    CP_COMMIT();
    for (int ch = 0; ch < NCH; ch++) {
        if (ch + 1 < NCH) { prefetch(ch + 1, (ch + 1) & 1); CP_COMMIT(); CP_WAIT(1); }
        else CP_WAIT(0);
        __syncthreads();
        const uint32_t* As = sm + (ch & 1) * ER_BUF;
        const uint32_t* Bs = As + 2560;
        #pragma unroll
        for (int ks = 0; ks < 2; ks++) {
            uint32_t af[2][4];
            #pragma unroll
            for (int mf = 0; mf < 2; mf++) {
                int r = warpM * 32 + mf * 16 + (lane >> 2);
                int c = ks * 8 + (lane & 3);
                af[mf][0] = As[r * 20 + c];
                af[mf][1] = As[(r + 8) * 20 + c];
                af[mf][2] = As[r * 20 + c + 4];
                af[mf][3] = As[(r + 8) * 20 + c + 4];
            }
            uint32_t bf[4][2];
            #pragma unroll
            for (int nf = 0; nf < 4; nf++) {
                int n = warpN * 32 + nf * 8 + (lane >> 2);
                int kk = ks * 8 + (lane & 3);
                bf[nf][0] = Bs[n * 20 + kk];
                bf[nf][1] = Bs[n * 20 + kk + 4];
            }
            #pragma unroll
            for (int mf = 0; mf < 2; mf++)
                #pragma unroll
                for (int nf = 0; nf < 4; nf++)
                    mma_f16(acc[mf][nf], af[mf], bf[nf]);
        }
        __syncthreads();
    }

    uint32_t* Bout = d_Bpad + (size_t)blockIdx.z * RPAD * KPAD2;
    #pragma unroll
    for (int mf = 0; mf < 2; mf++) {
        int r = row0 + warpM * 32 + mf * 16 + (lane >> 2);
        #pragma unroll
        for (int nf = 0; nf < 4; nf++) {
            int c = n0 + warpN * 32 + nf * 8 + (lane & 3) * 2;
            half2 h0 = __floats2half2_rn(acc[mf][nf][0], acc[mf][nf][1]);
            half2 h1 = __floats2half2_rn(acc[mf][nf][2], acc[mf][nf][3]);
            Bout[(size_t)r * KPAD2 + (c >> 1)]       = *reinterpret_cast<uint32_t*>(&h0);
            Bout[(size_t)(r + 8) * KPAD2 + (c >> 1)] = *reinterpret_cast<uint32_t*>(&h1);
        }
    }
}

// ===== phi via mma.sync fp16, 3 fused kinds; OUT = fp16 [i][j][p][q] ========
#define PHI_BUF 6400
__global__ void __launch_bounds__(256) phi_mma() {
    extern __shared__ uint32_t sm[];
    const int tid = threadIdx.x, lane = tid & 31, wid = tid >> 5;
    const int warpM = wid & 3, warpN = wid >> 2;
    const int row0 = blockIdx.y * 128;
    const int col0 = blockIdx.x * 64;
    const uint32_t smb = smem_u32(sm);
    const float4* Ag = (const float4*)(d_Apad + (size_t)row0 * KPAD2);
    float acc[3][2][4][4] = {};

    auto prefetch = [&](int ch, int buf) {
        int c4o = ch * 4;
        uint32_t base = smb + buf * PHI_BUF * 4;
        #pragma unroll
        for (int it = 0; it < 2; it++) {
            int idx = tid + it * 256;
            int m = idx >> 2, q = idx & 3;
            cpasync16(base + (m * 20 + q * 4) * 4, Ag + m * K4 + c4o + q);
        }
        #pragma unroll
        for (int it = 0; it < 3; it++) {
            int idx = tid + it * 256;
            int kb = idx >> 8, rem = idx & 255;
            int n = rem >> 2, q = rem & 3;
            const float4* Bg = (const float4*)(d_Bpad + (size_t)kb * RPAD * KPAD2
                                               + (size_t)col0 * KPAD2);
            cpasync16(base + (2560 + kb * 1280 + n * 20 + q * 4) * 4,
                      Bg + n * K4 + c4o + q);
        }
    };

    prefetch(0, 0);
    CP_COMMIT();
    for (int ch = 0; ch < NCH; ch++) {
        if (ch + 1 < NCH) { prefetch(ch + 1, (ch + 1) & 1); CP_COMMIT(); CP_WAIT(1); }
        else CP_WAIT(0);
        __syncthreads();
        const uint32_t* As = sm + (ch & 1) * PHI_BUF;
        #pragma unroll
        for (int ks = 0; ks < 2; ks++) {
            uint32_t af[2][4];
            #pragma unroll
            for (int mf = 0; mf < 2; mf++) {
                int r = warpM * 32 + mf * 16 + (lane >> 2);
                int c = ks * 8 + (lane & 3);
                af[mf][0] = As[r * 20 + c];
                af[mf][1] = As[(r + 8) * 20 + c];
                af[mf][2] = As[r * 20 + c + 4];
                af[mf][3] = As[(r + 8) * 20 + c + 4];
            }
            #pragma unroll
            for (int kb = 0; kb < 3; kb++) {
                const uint32_t* Bs = As + 2560 + kb * 1280;
                uint32_t bf[4][2];
                #pragma unroll
                for (int nf = 0; nf < 4; nf++) {
                    int n = warpN * 32 + nf * 8 + (lane >> 2);
                    int kk = ks * 8 + (lane & 3);
                    bf[nf][0] = Bs[n * 20 + kk];
                    bf[nf][1] = Bs[n * 20 + kk + 4];
                }
                #pragma unroll
                for (int mf = 0; mf < 2; mf++)
                    #pragma unroll
                    for (int nf = 0; nf < 4; nf++)
                        mma_f16(acc[kb][mf][nf], af[mf], bf[nf]);
            }
        }
        __syncthreads();
    }

    #pragma unroll
    for (int mf = 0; mf < 2; mf++) {
        #pragma unroll
        for (int half = 0; half < 2; half++) {
            int r = row0 + warpM * 32 + mf * 16 + (lane >> 2) + half * 8;
            if (r >= MC) continue;
            int i = r / C_, p = r % C_;
            #pragma unroll
            for (int nf = 0; nf < 4; nf++) {
                int c = col0 + warpN * 32 + nf * 8 + (lane & 3) * 2;
                if (c >= MC) continue;
                int j = c / C_, q = c % C_;
                const float* aw = d_a + (i * M_ + j) * 3;
                float w0 = aw[0], w1 = aw[1], w2 = aw[2];
                int e0 = half * 2;
                float v0 = acc[0][mf][nf][e0]     * w0 + acc[1][mf][nf][e0]     * w1
                         + acc[2][mf][nf][e0]     * w2;
                float v1 = acc[0][mf][nf][e0 + 1] * w0 + acc[1][mf][nf][e0 + 1] * w1
                         + acc[2][mf][nf][e0 + 1] * w2;
                half2 hv = __floats2half2_rn(v0, v1);
                *reinterpret_cast<uint32_t*>(
                    d_phi + ((size_t)(i * M_ + j) * (C_ * C_)) + p * C_ + q)
                    = *reinterpret_cast<uint32_t*>(&hv);
            }
        }
    }
}

// ============ cp.async double-buffered split-K fp32 GEMMs (unchanged) =======
__global__ void __launch_bounds__(256) gemm_nn_ca(
    const float* __restrict__ A, const float* __restrict__ B0,
    const float* __restrict__ B1, float* __restrict__ C0, float* __restrict__ C1,
    int M, int N, int K, int KC, int KS, long sB, long sC)
{
    __shared__ float As[2][64][20];
    __shared__ float Bs[2][16][64];
    const int batch = blockIdx.z / KS, kz = blockIdx.z % KS;
    const float* Bp = (batch == 0) ? B0 : B1 + (long)(batch - 1) * sB;
    float*       Cp = (batch == 0) ? C0 : C1 + (long)(batch - 1) * sC;
    const int tid = threadIdx.x;
    const int row0 = blockIdx.y * 64, col0 = blockIdx.x * 64;
    const int tm = (tid >> 4) * 4, tn = (tid & 15) * 4;
    const int k0 = kz * KC, kend = min(K, k0 + KC);
    if (k0 >= K) return;
    const int S = (kend - k0 + 15) >> 4;
    float acc[4][4] = {};

    auto prefetch = [&](int s, int buf) {
        int kb = k0 + s * 16;
        {
            int m = tid >> 2, q = tid & 3;
            int gr = row0 + m, gc = kb + q * 4;
            int bytes = (gr < M && gc < kend) ? min(16, (kend - gc) * 4) : 0;
            cpasync16z(smem_u32(&As[buf][m][q * 4]), A + (long)gr * K + gc, bytes);
        }
        {
            int kk = tid >> 4, q = tid & 15;
            int gr = kb + kk, gc = col0 + q * 4;
            int bytes = (gr < kend && gc < N) ? min(16, (N - gc) * 4) : 0;
            cpasync16z(smem_u32(&Bs[buf][kk][q * 4]), Bp + (long)gr * N + gc, bytes);
        }
    };

    prefetch(0, 0);
    CP_COMMIT();
    for (int s = 0; s < S; s++) {
        if (s + 1 < S) { prefetch(s + 1, (s + 1) & 1); CP_COMMIT(); CP_WAIT(1); }
        else CP_WAIT(0);
        __syncthreads();
        int buf = s & 1;
        #pragma unroll
        for (int kk = 0; kk < 16; kk++) {
            float a4[4], b4[4];
            #pragma unroll
            for (int x = 0; x < 4; x++) a4[x] = As[buf][tm + x][kk];
            #pragma unroll
            for (int y = 0; y < 4; y++) b4[y] = Bs[buf][kk][tn + y];
            #pragma unroll
            for (int x = 0; x < 4; x++)
                #pragma unroll
                for (int y = 0; y < 4; y++) acc[x][y] += a4[x] * b4[y];
        }
        __syncthreads();
    }
    #pragma unroll
    for (int x = 0; x < 4; x++) {
        int rr = row0 + tm + x;
        if (rr >= M) continue;
        #pragma unroll
        for (int y = 0; y < 4; y++) {
            int cc = col0 + tn + y;
            if (cc >= N) continue;
            atomicAdd(&Cp[(long)rr * N + cc], acc[x][y]);
        }
    }
}

__global__ void __launch_bounds__(256) gemm_nt_ca(
    const float* __restrict__ A, const float* __restrict__ B, float* __restrict__ C,
    int M, int N, int K, int KC, int KS, long sA, long sC)
{
    __shared__ float As[2][64][20];
    __shared__ float Bs[2][16][68];
    const int batch = blockIdx.z / KS, kz = blockIdx.z % KS;
    const float* Ap = A + (long)batch * sA;
    float*       Cp = C + (long)batch * sC;
    const int tid = threadIdx.x;
    const int row0 = blockIdx.y * 64, col0 = blockIdx.x * 64;
    const int tm = (tid >> 4) * 4, tn = (tid & 15) * 4;
    const int k0 = kz * KC, kend = min(K, k0 + KC);
    if (k0 >= K) return;
    const int S = (kend - k0 + 15) >> 4;
    float acc[4][4] = {};

    auto prefetch = [&](int s, int buf) {
        int kb = k0 + s * 16;
        {
            int m = tid >> 2, q = tid & 3;
            int gr = row0 + m, gc = kb + q * 4;
            int bytes = (gr < M && gc < kend) ? min(16, (kend - gc) * 4) : 0;
            cpasync16z(smem_u32(&As[buf][m][q * 4]), Ap + (long)gr * K + gc, bytes);
        }
        #pragma unroll
        for (int it = 0; it < 4; it++) {
            int idx = tid + it * 256;
            int n = idx >> 4, kk = idx & 15;
            int gr = col0 + n, gc = kb + kk;
            int bytes = (gr < N && gc < kend) ? 4 : 0;
            cpasync4z(smem_u32(&Bs[buf][kk][n]), B + (long)gr * K + gc, bytes);
        }
    };

    prefetch(0, 0);
    CP_COMMIT();
    for (int s = 0; s < S; s++) {
        if (s + 1 < S) { prefetch(s + 1, (s + 1) & 1); CP_COMMIT(); CP_WAIT(1); }
        else CP_WAIT(0);
        __syncthreads();
        int buf = s & 1;
        #pragma unroll
        for (int kk = 0; kk < 16; kk++) {
            float a4[4], b4[4];
            #pragma unroll
            for (int x = 0; x < 4; x++) a4[x] = As[buf][tm + x][kk];
            #pragma unroll
            for (int y = 0; y < 4; y++) b4[y] = Bs[buf][kk][tn + y];
            #pragma unroll
            for (int x = 0; x < 4; x++)
                #pragma unroll
                for (int y = 0; y < 4; y++) acc[x][y] += a4[x] * b4[y];
        }
        __syncthreads();
    }
    #pragma unroll
    for (int x = 0; x < 4; x++) {
        int rr = row0 + tm + x;
        if (rr >= M) continue;
        #pragma unroll
        for (int y = 0; y < 4; y++) {
            int cc = col0 + tn + y;
            if (cc >= N) continue;
            atomicAdd(&Cp[(long)rr * N + cc], acc[x][y]);
        }
    }
}

__global__ void ftanh(const float* __restrict__ bias) {
    int idx = blockIdx.x * blockDim.x + threadIdx.x;
    if (idx >= M_ * D_) return;
    d_f[idx] = tanhf(d_f[idx] + bias[idx % D_]);
}

// ---------------- a softmax (needed by phi) ----------------
__global__ void a_kernel()
{
    int ij = blockIdx.x * blockDim.x + threadIdx.x;
    if (ij >= MM) return;
    const float scale = 0.05773502691896258f;
    float s0 = d_s[0 * MM + ij] * scale;
    float s1 = d_s[1 * MM + ij] * scale;
    float s2 = d_s[2 * MM + ij] * scale;
    float mx = fmaxf(s0, fmaxf(s1, s2));
    float e0 = expf(s0 - mx), e1 = expf(s1 - mx), e2 = expf(s2 - mx);
    float inv = 1.f / (e0 + e1 + e2);
    d_a[ij * 3 + 0] = e0 * inv;
    d_a[ij * 3 + 1] = e1 * inv;
    d_a[ij * 3 + 2] = e2 * inv;
}

// ---------------- psi (needed only by LBP; overlaps phi) ----------------
__global__ void psi_kernel(const float* __restrict__ ent)
{
    int m = blockIdx.x;
    __shared__ float gs[D_];
    for (int d = threadIdx.x; d < D_; d += blockDim.x) gs[d] = d_g[m * D_ + d];
    __syncthreads();
    int w = threadIdx.x >> 5, lane = threadIdx.x & 31;
    for (int c = w; c < C_; c += (blockDim.x >> 5)) {
        const float* e = ent + ((long)m * C_ + c) * D_;
        float s = 0.f;
        for (int d = lane; d < D_; d += 32) s += e[d] * gs[d];
        #pragma unroll
        for (int o = 16; o; o >>= 1) s += __shfl_down_sync(0xffffffffu, s, o);
        if (lane == 0) d_psi[m * C_ + c] = s;
    }
}

// ---------------- fused LBP iteration: half2/float2 vectorized --------------
// Lane l < 15 owns q-pair (2l, 2l+1). Halved LDG transaction count vs scalar.
__global__ void __launch_bounds__(320) lbp_fused(
    const float* __restrict__ mb_src, float* __restrict__ mb_dst,
    const float* __restrict__ stot_src, float* __restrict__ stot_dst,
    float* __restrict__ stot_zero)
{
    const int tid = threadIdx.x;
    const int w = tid >> 5, lane = tid & 31;
    const int b = blockIdx.x;
    const int j = b % M_;
    const int i = (b / M_) * 10 + w;
    __shared__ float tt[10][32];
    __shared__ float sred[10][32];

    if (b < 12) {
        int z = b * 320 + tid;
        if (z < M_ * C_) stot_zero[z] = 0.f;
    }

    // tt[p] = psi[i,p] + stot[i,p] - mbar[j->i][p], loaded as float2 pairs
    if (lane < 15) {
        float2 ps = *(const float2*)&d_psi[i * C_ + lane * 2];
        float2 st = *(const float2*)&stot_src[i * C_ + lane * 2];
        float2 mb = *(const float2*)&mb_src[(j * M_ + i) * C_ + lane * 2];
        tt[w][lane * 2]     = ps.x + st.x - mb.x;
        tt[w][lane * 2 + 1] = ps.y + st.y - mb.y;
    }
    __syncwarp();

    // max over p: half2 loads, 15 per row
    const __half2* ph2 = (const __half2*)(d_phi + (size_t)(i * M_ + j) * (C_ * C_));
    float mv0 = -1e30f, mv1 = -1e30f;
    if (lane < 15) {
        #pragma unroll 6
        for (int p = 0; p < C_; p++) {
            float2 f2 = __half22float2(ph2[p * 15 + lane]);
            float t = tt[w][p];
            mv0 = fmaxf(mv0, t + f2.x);
            mv1 = fmaxf(mv1, t + f2.y);
        }
        mv0 = fmaxf(mv0, 0.f);
        mv1 = fmaxf(mv1, 0.f);
    }
    // softmax over 30 q (2 per lane, lanes 0-14)
    float mx = fmaxf(mv0, mv1);          // lanes >=15 hold -1e30
    #pragma unroll
    for (int o = 16; o; o >>= 1) mx = fmaxf(mx, __shfl_xor_sync(0xffffffffu, mx, o));
    float e0 = (lane < 15) ? __expf(mv0 - mx) : 0.f;
    float e1 = (lane < 15) ? __expf(mv1 - mx) : 0.f;
    float sum = e0 + e1;
    #pragma unroll
    for (int o = 16; o; o >>= 1) sum += __shfl_xor_sync(0xffffffffu, sum, o);

    float nm0 = 0.f, nm1 = 0.f;
    if (lane < 15) {
        float inv = 1.f / sum;
        float2 old = *(const float2*)&mb_src[(i * M_ + j) * C_ + lane * 2];
        nm0 = __logf(0.5f * __expf(old.x) + 0.5f * e0 * inv);
        nm1 = __logf(0.5f * __expf(old.y) + 0.5f * e1 * inv);
        *(float2*)&mb_dst[(i * M_ + j) * C_ + lane * 2] = make_float2(nm0, nm1);
        sred[w][lane * 2]     = nm0;
        sred[w][lane * 2 + 1] = nm1;
    }
    __syncthreads();

    if (tid < C_) {
        float s = 0.f;
        #pragma unroll
        for (int w2 = 0; w2 < 10; w2++) s += sred[w2][tid];
        atomicAdd(&stot_dst[j * C_ + tid], s);
    }
}

__global__ void final_kernel(float* __restrict__ out, const float* __restrict__ mbar,
                             const float* __restrict__ stot)
{
    int i = blockIdx.x;
    int lane = threadIdx.x;
    float u = -1e30f;
    if (lane < C_)
        u = d_psi[i * C_ + lane] + stot[i * C_ + lane]
          - mbar[(i * M_ + i) * C_ + lane];
    float mx = u;
    #pragma unroll
    for (int o = 16; o; o >>= 1) mx = fmaxf(mx, __shfl_xor_sync(0xffffffffu, mx, o));
    float e = (lane < C_) ? expf(u - mx) : 0.f;
    float sum = e;
    #pragma unroll
    for (int o = 16; o; o >>= 1) sum += __shfl_xor_sync(0xffffffffu, sum, o);
    if (lane < C_) out[i * C_ + lane] = e / sum;
}

// ---------------- host ----------------
extern "C" void kernel_launch(void* const* d_in, const int* in_sizes, int n_in,
                              void* d_out, int out_size)
{
    const float* ent    = (const float*)d_in[0];
    const float* fmc_in = (const float*)d_in[1];
    const float* W_fmc  = (const float*)d_in[2];
    const float* b_fmc  = (const float*)d_in[3];
    const float* Bmat   = (const float*)d_in[4];
    const float* Rmat   = (const float*)d_in[5];
    const float* Dmat   = (const float*)d_in[6];
    float* out = (float*)d_out;

    float *pf, *pg, *pfD, *ps, *pmA, *pmB, *pS, *pBt;
    cudaGetSymbolAddress((void**)&pf,  d_f);
    cudaGetSymbolAddress((void**)&pg,  d_g);
    cudaGetSymbolAddress((void**)&pfD, d_fD);
    cudaGetSymbolAddress((void**)&ps,  d_s);
    cudaGetSymbolAddress((void**)&pmA, d_mbarA);
    cudaGetSymbolAddress((void**)&pmB, d_mbarB);
    cudaGetSymbolAddress((void**)&pS,  d_S);
    cudaGetSymbolAddress((void**)&pBt, d_Bt);
    float* S[3] = { pS, pS + M_*C_, pS + 2*M_*C_ };

    // one-time stream/event setup (first call = correctness run, not capture)
    static cudaStream_t s_side = nullptr;
    static cudaEvent_t ev_fork = nullptr, ev_join = nullptr, ev_psi = nullptr;
    if (s_side == nullptr) {
        cudaStreamCreateWithFlags(&s_side, cudaStreamNonBlocking);
        cudaEventCreateWithFlags(&ev_fork, cudaEventDisableTiming);
        cudaEventCreateWithFlags(&ev_join, cudaEventDisableTiming);
        cudaEventCreateWithFlags(&ev_psi,  cudaEventDisableTiming);
        cudaFuncSetAttribute(er_mma,  cudaFuncAttributeMaxDynamicSharedMemorySize, 2 * ER_BUF * 4);
        cudaFuncSetAttribute(phi_mma, cudaFuncAttributeMaxDynamicSharedMemorySize, 2 * PHI_BUF * 4);
    }
    const cudaStream_t mainS = cudaStreamPerThread;

    // fork: side stream runs the front chain concurrently with pack_er + er_mma
    cudaEventRecord(ev_fork, mainS);
    cudaStreamWaitEvent(s_side, ev_fork, 0);

    // ---- side stream: zeros/Bt + f -> tanh -> g+fD -> s -> a ; then psi ----
    pack_front<<<256, 256, 0, s_side>>>(Bmat);
    gemm_nn_ca<<<dim3(5, 2, 15), 256, 0, s_side>>>(fmc_in, W_fmc, nullptr, pf, nullptr,
                                                   100, 300, 900, 64, 15, 0, 0);
    ftanh<<<(M_ * D_ + 255) / 256, 256, 0, s_side>>>(b_fmc);
    gemm_nn_ca<<<dim3(5, 2, 20), 256, 0, s_side>>>(pf, pBt, Dmat, pg, pfD,
                                                   100, 300, 300, 64, 5, 90000, 30000);
    gemm_nt_ca<<<dim3(2, 2, 15), 256, 0, s_side>>>(pfD, pf, ps, 100, 100, 300, 64, 5,
                                                   30000, 10000);
    a_kernel<<<40, 256, 0, s_side>>>();
    cudaEventRecord(ev_join, s_side);            // phi needs only d_a from here
    psi_kernel<<<100, 256, 0, s_side>>>(ent);    // overlaps phi_mma
    cudaEventRecord(ev_psi, s_side);

    // ---- main stream: pack_er -> er_mma ----
    pack_er<<<256, 256, 0, mainS>>>(ent, Rmat);
    er_mma<<<dim3(5, 24, 3), 256, 2 * ER_BUF * 4, mainS>>>();

    // join: phi needs d_a (side) + d_Bpad (main)
    cudaStreamWaitEvent(mainS, ev_join, 0);
    phi_mma<<<dim3(47, 24), 256, 2 * PHI_BUF * 4, mainS>>>();

    // LBP needs psi
    cudaStreamWaitEvent(mainS, ev_psi, 0);
    for (int it = 0; it < 10; it++) {
        const float* msrc = (it & 1) ? pmB : pmA;
        float*       mdst = (it & 1) ? pmA : pmB;
        lbp_fused<<<1000, 320, 0, mainS>>>(msrc, mdst,
                                           S[it % 3], S[(it + 1) % 3], S[(it + 2) % 3]);
    }
    final_kernel<<<100, 32, 0, mainS>>>(out, pmA, S[1]);
}

// round 15
// speedup vs baseline: 1.1002x; 1.0131x over previous
#include <cuda_runtime.h>
#include <cuda_fp16.h>
#include <cstdint>
#include <math.h>

#define M_    100
#define C_    30
#define D_    300
#define K_    3
#define MC    3000
#define MM    10000
#define KPAD2 160            // half2 per row (320 fp16, padded from 300)
#define K4    40             // float4 per row (640 B)
#define RPAD  3072           // padded MC rows
#define NPAD  320            // padded rows for R^T (e dim)
#define NCH   10             // chunks of 16 half2 (32 fp16 k-values)

// ---------------- scratch ----------------
static __device__ float    d_f   [M_*D_];
static __device__ float    d_g   [M_*D_];
static __device__ float    d_psi [M_*C_];
static __device__ float    d_fD  [K_*M_*D_];
static __device__ float    d_s   [K_*M_*M_];
static __device__ float    d_a   [M_*M_*K_];
static __device__ float    d_Bt  [D_*D_];          // B^T (fp32 exact)
static __device__ uint32_t d_Apad[RPAD*KPAD2];     // ent, fp16x2, padded
static __device__ uint32_t d_Bpad[K_*RPAD*KPAD2];  // ER_k, fp16x2
static __device__ uint32_t d_Rt  [K_*NPAD*KPAD2];  // R_k^T, fp16x2
static __device__ __half   d_phi [MM*C_*C_];       // 18 MB, fp16, [i][j][p][q]
static __device__ float    d_mbarA[M_*M_*C_];
static __device__ float    d_mbarB[M_*M_*C_];
static __device__ float    d_S   [3][M_*C_];       // rotating stot buffers

// ---------------- helpers ----------------
__device__ __forceinline__ uint32_t smem_u32(const void* p) {
    uint32_t a;
    asm("{ .reg .u64 t; cvta.to.shared.u64 t, %1; cvt.u32.u64 %0, t; }" : "=r"(a) : "l"(p));
    return a;
}
__device__ __forceinline__ void cpasync16(uint32_t dst, const void* src) {
    asm volatile("{\n\t.reg .u64 g;\n\tcvta.to.global.u64 g, %1;\n\t"
                 "cp.async.cg.shared.global [%0], [g], 16;\n\t}"
                 :: "r"(dst), "l"(src));
}
__device__ __forceinline__ void cpasync16z(uint32_t dst, const void* src, int bytes) {
    asm volatile("{\n\t.reg .u64 g;\n\tcvta.to.global.u64 g, %1;\n\t"
                 "cp.async.cg.shared.global [%0], [g], 16, %2;\n\t}"
                 :: "r"(dst), "l"(src), "r"(bytes));
}
__device__ __forceinline__ void cpasync4z(uint32_t dst, const void* src, int bytes) {
    asm volatile("{\n\t.reg .u64 g;\n\tcvta.to.global.u64 g, %1;\n\t"
                 "cp.async.ca.shared.global [%0], [g], 4, %2;\n\t}"
                 :: "r"(dst), "l"(src), "r"(bytes));
}
#define CP_COMMIT() asm volatile("cp.async.commit_group;" ::: "memory")
#define CP_WAIT(n)  asm volatile("cp.async.wait_group %0;" :: "n"(n) : "memory")

__device__ __forceinline__ void mma_f16(float* c, const uint32_t* a, const uint32_t* b) {
    asm volatile("mma.sync.aligned.m16n8k16.row.col.f32.f16.f16.f32 "
        "{%0,%1,%2,%3}, {%4,%5,%6,%7}, {%8,%9}, {%0,%1,%2,%3};"
        : "+f"(c[0]), "+f"(c[1]), "+f"(c[2]), "+f"(c[3])
        : "r"(a[0]), "r"(a[1]), "r"(a[2]), "r"(a[3]), "r"(b[0]), "r"(b[1]));
}

// ---------------- pack_front: zeros + Bt (side stream) ----------------------
__global__ void pack_front(const float* __restrict__ Bm) {
    int idx = blockIdx.x * blockDim.x + threadIdx.x;
    int stride = gridDim.x * blockDim.x;
    for (int i = idx; i < M_*D_; i += stride) { d_f[i] = 0.f; d_g[i] = 0.f; }
    for (int i = idx; i < K_*M_*D_; i += stride) d_fD[i] = 0.f;
    for (int i = idx; i < K_*MM; i += stride) d_s[i] = 0.f;
    for (int i = idx; i < M_*M_*C_; i += stride) d_mbarA[i] = 0.f;
    for (int i = idx; i < M_*C_; i += stride) { d_S[0][i] = 0.f; d_S[1][i] = 0.f; }
    for (int i = idx; i < D_*D_; i += stride) {
        int dd = i / D_, e = i - dd * D_;
        d_Bt[i] = Bm[e * D_ + dd];
    }
}
// ---------------- pack_er: fp16 Apad + Rt (main stream) ---------------------
__global__ void pack_er(const float* __restrict__ ent, const float* __restrict__ R) {
    int idx = blockIdx.x * blockDim.x + threadIdx.x;
    int stride = gridDim.x * blockDim.x;
    for (int i = idx; i < RPAD*KPAD2; i += stride) {
        int r = i / KPAD2, c2 = i - r * KPAD2;
        int d0 = c2 * 2;
        float x = (r < MC && d0     < D_) ? ent[r * D_ + d0]     : 0.f;
        float y = (r < MC && d0 + 1 < D_) ? ent[r * D_ + d0 + 1] : 0.f;
        half2 h = __floats2half2_rn(x, y);
        d_Apad[i] = *reinterpret_cast<uint32_t*>(&h);
    }
    for (int i = idx; i < K_*NPAD*KPAD2; i += stride) {
        int k = i / (NPAD * KPAD2);
        int rem = i - k * (NPAD * KPAD2);
        int n = rem / KPAD2, c2 = rem - n * KPAD2;
        int d0 = c2 * 2;
        float x = (n < D_ && d0     < D_) ? R[k * D_ * D_ + d0       * D_ + n] : 0.f;
        float y = (n < D_ && d0 + 1 < D_) ? R[k * D_ * D_ + (d0 + 1) * D_ + n] : 0.f;
        half2 h = __floats2half2_rn(x, y);
        d_Rt[i] = *reinterpret_cast<uint32_t*>(&h);
    }
}

// ================= ER via mma.sync fp16 (unchanged) ====================
#define ER_BUF 3840
__global__ void __launch_bounds__(256) er_mma() {
    extern __shared__ uint32_t sm[];
    const int tid = threadIdx.x, lane = tid & 31, wid = tid >> 5;
    const int warpM = wid & 3, warpN = wid >> 2;
    const int row0 = blockIdx.y * 128;
    const int n0   = blockIdx.x * 64;
    const uint32_t smb = smem_u32(sm);
    const float4* Ag = (const float4*)(d_Apad + (size_t)row0 * KPAD2);
    const float4* Bg = (const float4*)(d_Rt + (size_t)blockIdx.z * NPAD * KPAD2
                                       + (size_t)n0 * KPAD2);
    float acc[2][4][4] = {};

    auto prefetch = [&](int ch, int buf) {
        int c4o = ch * 4;
        uint32_t base = smb + buf * ER_BUF * 4;
        #pragma unroll
        for (int it = 0; it < 2; it++) {
            int idx = tid + it * 256;
            int m = idx >> 2, q = idx & 3;
            cpasync16(base + (m * 20 + q * 4) * 4, Ag + m * K4 + c4o + q);
        }
        {
            int n = tid >> 2, q = tid & 3;
            cpasync16(base + (2560 + n * 20 + q * 4) * 4, Bg + n * K4 + c4o + q);
        }
    };

    prefetch(0, 0);
    CP_COMMIT();
    for (int ch = 0; ch < NCH; ch++) {
        if (ch + 1 < NCH) { prefetch(ch + 1, (ch + 1) & 1); CP_COMMIT(); CP_WAIT(1); }
        else CP_WAIT(0);
        __syncthreads();
        const uint32_t* As = sm + (ch & 1) * ER_BUF;
        const uint32_t* Bs = As + 2560;
        #pragma unroll
        for (int ks = 0; ks < 2; ks++) {
            uint32_t af[2][4];
            #pragma unroll
            for (int mf = 0; mf < 2; mf++) {
                int r = warpM * 32 + mf * 16 + (lane >> 2);
                int c = ks * 8 + (lane & 3);
                af[mf][0] = As[r * 20 + c];
                af[mf][1] = As[(r + 8) * 20 + c];
                af[mf][2] = As[r * 20 + c + 4];
                af[mf][3] = As[(r + 8) * 20 + c + 4];
            }
            uint32_t bf[4][2];
            #pragma unroll
            for (int nf = 0; nf < 4; nf++) {
                int n = warpN * 32 + nf * 8 + (lane >> 2);
                int kk = ks * 8 + (lane & 3);
                bf[nf][0] = Bs[n * 20 + kk];
                bf[nf][1] = Bs[n * 20 + kk + 4];
            }
            #pragma unroll
            for (int mf = 0; mf < 2; mf++)
                #pragma unroll
                for (int nf = 0; nf < 4; nf++)
                    mma_f16(acc[mf][nf], af[mf], bf[nf]);
        }
        __syncthreads();
    }

    uint32_t* Bout = d_Bpad + (size_t)blockIdx.z * RPAD * KPAD2;
    #pragma unroll
    for (int mf = 0; mf < 2; mf++) {
        int r = row0 + warpM * 32 + mf * 16 + (lane >> 2);
        #pragma unroll
        for (int nf = 0; nf < 4; nf++) {
            int c = n0 + warpN * 32 + nf * 8 + (lane & 3) * 2;
            half2 h0 = __floats2half2_rn(acc[mf][nf][0], acc[mf][nf][1]);
            half2 h1 = __floats2half2_rn(acc[mf][nf][2], acc[mf][nf][3]);
            Bout[(size_t)r * KPAD2 + (c >> 1)]       = *reinterpret_cast<uint32_t*>(&h0);
            Bout[(size_t)(r + 8) * KPAD2 + (c >> 1)] = *reinterpret_cast<uint32_t*>(&h1);
        }
    }
}

// ===== phi via mma.sync fp16, 3 fused kinds; OUT = fp16 [i][j][p][q] ========
#define PHI_BUF 6400
__global__ void __launch_bounds__(256) phi_mma() {
    extern __shared__ uint32_t sm[];
    const int tid = threadIdx.x, lane = tid & 31, wid = tid >> 5;
    const int warpM = wid & 3, warpN = wid >> 2;
    const int row0 = blockIdx.y * 128;
    const int col0 = blockIdx.x * 64;
    const uint32_t smb = smem_u32(sm);
    const float4* Ag = (const float4*)(d_Apad + (size_t)row0 * KPAD2);
    float acc[3][2][4][4] = {};

    auto prefetch = [&](int ch, int buf) {
        int c4o = ch * 4;
        uint32_t base = smb + buf * PHI_BUF * 4;
        #pragma unroll
        for (int it = 0; it < 2; it++) {
            int idx = tid + it * 256;
            int m = idx >> 2, q = idx & 3;
            cpasync16(base + (m * 20 + q * 4) * 4, Ag + m * K4 + c4o + q);
        }
        #pragma unroll
        for (int it = 0; it < 3; it++) {
            int idx = tid + it * 256;
            int kb = idx >> 8, rem = idx & 255;
            int n = rem >> 2, q = rem & 3;
            const float4* Bg = (const float4*)(d_Bpad + (size_t)kb * RPAD * KPAD2
                                               + (size_t)col0 * KPAD2);
            cpasync16(base + (2560 + kb * 1280 + n * 20 + q * 4) * 4,
                      Bg + n * K4 + c4o + q);
        }
    };

    prefetch(0, 0);
    CP_COMMIT();
    for (int ch = 0; ch < NCH; ch++) {
        if (ch + 1 < NCH) { prefetch(ch + 1, (ch + 1) & 1); CP_COMMIT(); CP_WAIT(1); }
        else CP_WAIT(0);
        __syncthreads();
        const uint32_t* As = sm + (ch & 1) * PHI_BUF;
        #pragma unroll
        for (int ks = 0; ks < 2; ks++) {
            uint32_t af[2][4];
            #pragma unroll
            for (int mf = 0; mf < 2; mf++) {
                int r = warpM * 32 + mf * 16 + (lane >> 2);
                int c = ks * 8 + (lane & 3);
                af[mf][0] = As[r * 20 + c];
                af[mf][1] = As[(r + 8) * 20 + c];
                af[mf][2] = As[r * 20 + c + 4];
                af[mf][3] = As[(r + 8) * 20 + c + 4];
            }
            #pragma unroll
            for (int kb = 0; kb < 3; kb++) {
                const uint32_t* Bs = As + 2560 + kb * 1280;
                uint32_t bf[4][2];
                #pragma unroll
                for (int nf = 0; nf < 4; nf++) {
                    int n = warpN * 32 + nf * 8 + (lane >> 2);
                    int kk = ks * 8 + (lane & 3);
                    bf[nf][0] = Bs[n * 20 + kk];
                    bf[nf][1] = Bs[n * 20 + kk + 4];
                }
                #pragma unroll
                for (int mf = 0; mf < 2; mf++)
                    #pragma unroll
                    for (int nf = 0; nf < 4; nf++)
                        mma_f16(acc[kb][mf][nf], af[mf], bf[nf]);
            }
        }
        __syncthreads();
    }

    #pragma unroll
    for (int mf = 0; mf < 2; mf++) {
        #pragma unroll
        for (int half = 0; half < 2; half++) {
            int r = row0 + warpM * 32 + mf * 16 + (lane >> 2) + half * 8;
            if (r >= MC) continue;
            int i = r / C_, p = r % C_;
            #pragma unroll
            for (int nf = 0; nf < 4; nf++) {
                int c = col0 + warpN * 32 + nf * 8 + (lane & 3) * 2;
                if (c >= MC) continue;
                int j = c / C_, q = c % C_;
                const float* aw = d_a + (i * M_ + j) * 3;
                float w0 = aw[0], w1 = aw[1], w2 = aw[2];
                int e0 = half * 2;
                float v0 = acc[0][mf][nf][e0]     * w0 + acc[1][mf][nf][e0]     * w1
                         + acc[2][mf][nf][e0]     * w2;
                float v1 = acc[0][mf][nf][e0 + 1] * w0 + acc[1][mf][nf][e0 + 1] * w1
                         + acc[2][mf][nf][e0 + 1] * w2;
                half2 hv = __floats2half2_rn(v0, v1);
                *reinterpret_cast<uint32_t*>(
                    d_phi + ((size_t)(i * M_ + j) * (C_ * C_)) + p * C_ + q)
                    = *reinterpret_cast<uint32_t*>(&hv);
            }
        }
    }
}

// ============ cp.async double-buffered split-K fp32 GEMMs (unchanged) =======
__global__ void __launch_bounds__(256) gemm_nn_ca(
    const float* __restrict__ A, const float* __restrict__ B0,
    const float* __restrict__ B1, float* __restrict__ C0, float* __restrict__ C1,
    int M, int N, int K, int KC, int KS, long sB, long sC)
{
    __shared__ float As[2][64][20];
    __shared__ float Bs[2][16][64];
    const int batch = blockIdx.z / KS, kz = blockIdx.z % KS;
    const float* Bp = (batch == 0) ? B0 : B1 + (long)(batch - 1) * sB;
    float*       Cp = (batch == 0) ? C0 : C1 + (long)(batch - 1) * sC;
    const int tid = threadIdx.x;
    const int row0 = blockIdx.y * 64, col0 = blockIdx.x * 64;
    const int tm = (tid >> 4) * 4, tn = (tid & 15) * 4;
    const int k0 = kz * KC, kend = min(K, k0 + KC);
    if (k0 >= K) return;
    const int S = (kend - k0 + 15) >> 4;
    float acc[4][4] = {};

    auto prefetch = [&](int s, int buf) {
        int kb = k0 + s * 16;
        {
            int m = tid >> 2, q = tid & 3;
            int gr = row0 + m, gc = kb + q * 4;
            int bytes = (gr < M && gc < kend) ? min(16, (kend - gc) * 4) : 0;
            cpasync16z(smem_u32(&As[buf][m][q * 4]), A + (long)gr * K + gc, bytes);
        }
        {
            int kk = tid >> 4, q = tid & 15;
            int gr = kb + kk, gc = col0 + q * 4;
            int bytes = (gr < kend && gc < N) ? min(16, (N - gc) * 4) : 0;
            cpasync16z(smem_u32(&Bs[buf][kk][q * 4]), Bp + (long)gr * N + gc, bytes);
        }
    };

    prefetch(0, 0);
    CP_COMMIT();
    for (int s = 0; s < S; s++) {
        if (s + 1 < S) { prefetch(s + 1, (s + 1) & 1); CP_COMMIT(); CP_WAIT(1); }
        else CP_WAIT(0);
        __syncthreads();
        int buf = s & 1;
        #pragma unroll
        for (int kk = 0; kk < 16; kk++) {
            float a4[4], b4[4];
            #pragma unroll
            for (int x = 0; x < 4; x++) a4[x] = As[buf][tm + x][kk];
            #pragma unroll
            for (int y = 0; y < 4; y++) b4[y] = Bs[buf][kk][tn + y];
            #pragma unroll
            for (int x = 0; x < 4; x++)
                #pragma unroll
                for (int y = 0; y < 4; y++) acc[x][y] += a4[x] * b4[y];
        }
        __syncthreads();
    }
    #pragma unroll
    for (int x = 0; x < 4; x++) {
        int rr = row0 + tm + x;
        if (rr >= M) continue;
        #pragma unroll
        for (int y = 0; y < 4; y++) {
            int cc = col0 + tn + y;
            if (cc >= N) continue;
            atomicAdd(&Cp[(long)rr * N + cc], acc[x][y]);
        }
    }
}

__global__ void __launch_bounds__(256) gemm_nt_ca(
    const float* __restrict__ A, const float* __restrict__ B, float* __restrict__ C,
    int M, int N, int K, int KC, int KS, long sA, long sC)
{
    __shared__ float As[2][64][20];
    __shared__ float Bs[2][16][68];
    const int batch = blockIdx.z / KS, kz = blockIdx.z % KS;
    const float* Ap = A + (long)batch * sA;
    float*       Cp = C + (long)batch * sC;
    const int tid = threadIdx.x;
    const int row0 = blockIdx.y * 64, col0 = blockIdx.x * 64;
    const int tm = (tid >> 4) * 4, tn = (tid & 15) * 4;
    const int k0 = kz * KC, kend = min(K, k0 + KC);
    if (k0 >= K) return;
    const int S = (kend - k0 + 15) >> 4;
    float acc[4][4] = {};

    auto prefetch = [&](int s, int buf) {
        int kb = k0 + s * 16;
        {
            int m = tid >> 2, q = tid & 3;
            int gr = row0 + m, gc = kb + q * 4;
            int bytes = (gr < M && gc < kend) ? min(16, (kend - gc) * 4) : 0;
            cpasync16z(smem_u32(&As[buf][m][q * 4]), Ap + (long)gr * K + gc, bytes);
        }
        #pragma unroll
        for (int it = 0; it < 4; it++) {
            int idx = tid + it * 256;
            int n = idx >> 4, kk = idx & 15;
            int gr = col0 + n, gc = kb + kk;
            int bytes = (gr < N && gc < kend) ? 4 : 0;
            cpasync4z(smem_u32(&Bs[buf][kk][n]), B + (long)gr * K + gc, bytes);
        }
    };

    prefetch(0, 0);
    CP_COMMIT();
    for (int s = 0; s < S; s++) {
        if (s + 1 < S) { prefetch(s + 1, (s + 1) & 1); CP_COMMIT(); CP_WAIT(1); }
        else CP_WAIT(0);
        __syncthreads();
        int buf = s & 1;
        #pragma unroll
        for (int kk = 0; kk < 16; kk++) {
            float a4[4], b4[4];
            #pragma unroll
            for (int x = 0; x < 4; x++) a4[x] = As[buf][tm + x][kk];
            #pragma unroll
            for (int y = 0; y < 4; y++) b4[y] = Bs[buf][kk][tn + y];
            #pragma unroll
            for (int x = 0; x < 4; x++)
                #pragma unroll
                for (int y = 0; y < 4; y++) acc[x][y] += a4[x] * b4[y];
        }
        __syncthreads();
    }
    #pragma unroll
    for (int x = 0; x < 4; x++) {
        int rr = row0 + tm + x;
        if (rr >= M) continue;
        #pragma unroll
        for (int y = 0; y < 4; y++) {
            int cc = col0 + tn + y;
            if (cc >= N) continue;
            atomicAdd(&Cp[(long)rr * N + cc], acc[x][y]);
        }
    }
}

__global__ void ftanh(const float* __restrict__ bias) {
    int idx = blockIdx.x * blockDim.x + threadIdx.x;
    if (idx >= M_ * D_) return;
    d_f[idx] = tanhf(d_f[idx] + bias[idx % D_]);
}

// ---------------- a softmax (needed by phi) ----------------
__global__ void a_kernel()
{
    int ij = blockIdx.x * blockDim.x + threadIdx.x;
    if (ij >= MM) return;
    const float scale = 0.05773502691896258f;
    float s0 = d_s[0 * MM + ij] * scale;
    float s1 = d_s[1 * MM + ij] * scale;
    float s2 = d_s[2 * MM + ij] * scale;
    float mx = fmaxf(s0, fmaxf(s1, s2));
    float e0 = expf(s0 - mx), e1 = expf(s1 - mx), e2 = expf(s2 - mx);
    float inv = 1.f / (e0 + e1 + e2);
    d_a[ij * 3 + 0] = e0 * inv;
    d_a[ij * 3 + 1] = e1 * inv;
    d_a[ij * 3 + 2] = e2 * inv;
}

// ---------------- psi (needed only by LBP; overlaps phi) ----------------
__global__ void psi_kernel(const float* __restrict__ ent)
{
    int m = blockIdx.x;
    __shared__ float gs[D_];
    for (int d = threadIdx.x; d < D_; d += blockDim.x) gs[d] = d_g[m * D_ + d];
    __syncthreads();
    int w = threadIdx.x >> 5, lane = threadIdx.x & 31;
    for (int c = w; c < C_; c += (blockDim.x >> 5)) {
        const float* e = ent + ((long)m * C_ + c) * D_;
        float s = 0.f;
        for (int d = lane; d < D_; d += 32) s += e[d] * gs[d];
        #pragma unroll
        for (int o = 16; o; o >>= 1) s += __shfl_down_sync(0xffffffffu, s, o);
        if (lane == 0) d_psi[m * C_ + c] = s;
    }
}

// ---------------- fused LBP iteration: 500 blocks, 2 units each -------------
// Single wave (500 < ~592 residency slots at 320 thr, 4/SM). Unit u: receiver
// j = u%100, senders i = (u/100)*10 + warp.
__global__ void __launch_bounds__(320) lbp_fused(
    const float* __restrict__ mb_src, float* __restrict__ mb_dst,
    const float* __restrict__ stot_src, float* __restrict__ stot_dst,
    float* __restrict__ stot_zero)
{
    const int tid = threadIdx.x;
    const int w = tid >> 5, lane = tid & 31;
    const int b = blockIdx.x;
    __shared__ float tt[10][32];
    __shared__ float sred[10][32];

    if (b < 12) {
        int z = b * 320 + tid;
        if (z < M_ * C_) stot_zero[z] = 0.f;
    }

    #pragma unroll
    for (int rep = 0; rep < 2; rep++) {
        const int unit = b + rep * 500;
        const int j = unit % M_;
        const int i = (unit / M_) * 10 + w;

        if (lane < C_)
            tt[w][lane] = d_psi[i * C_ + lane] + stot_src[i * C_ + lane]
                        - mb_src[(j * M_ + i) * C_ + lane];
        __syncwarp();

        const __half* ph = d_phi + (size_t)(i * M_ + j) * (C_ * C_);
        float mv = -1e30f;
        if (lane < C_) {
            #pragma unroll 6
            for (int p = 0; p < C_; p++)
                mv = fmaxf(mv, tt[w][p] + __half2float(ph[p * C_ + lane]));
            mv = fmaxf(mv, 0.f);
        }
        float mx = (lane < C_) ? mv : -1e30f;
        #pragma unroll
        for (int o = 16; o; o >>= 1) mx = fmaxf(mx, __shfl_xor_sync(0xffffffffu, mx, o));
        float e = (lane < C_) ? __expf(mv - mx) : 0.f;
        float sum = e;
        #pragma unroll
        for (int o = 16; o; o >>= 1) sum += __shfl_xor_sync(0xffffffffu, sum, o);

        float newm = 0.f;
        if (lane < C_) {
            float sm = e / sum;
            float old = mb_src[(i * M_ + j) * C_ + lane];
            newm = __logf(0.5f * __expf(old) + 0.5f * sm);
            mb_dst[(i * M_ + j) * C_ + lane] = newm;
        }
        sred[w][lane] = newm;
        __syncthreads();

        if (tid < C_) {
            float s = 0.f;
            #pragma unroll
            for (int w2 = 0; w2 < 10; w2++) s += sred[w2][tid];
            atomicAdd(&stot_dst[j * C_ + tid], s);
        }
        if (rep == 0) __syncthreads();   // protect smem reuse for unit 2
    }
}

__global__ void final_kernel(float* __restrict__ out, const float* __restrict__ mbar,
                             const float* __restrict__ stot)
{
    int i = blockIdx.x;
    int lane = threadIdx.x;
    float u = -1e30f;
    if (lane < C_)
        u = d_psi[i * C_ + lane] + stot[i * C_ + lane]
          - mbar[(i * M_ + i) * C_ + lane];
    float mx = u;
    #pragma unroll
    for (int o = 16; o; o >>= 1) mx = fmaxf(mx, __shfl_xor_sync(0xffffffffu, mx, o));
    float e = (lane < C_) ? expf(u - mx) : 0.f;
    float sum = e;
    #pragma unroll
    for (int o = 16; o; o >>= 1) sum += __shfl_xor_sync(0xffffffffu, sum, o);
    if (lane < C_) out[i * C_ + lane] = e / sum;
}

// ---------------- host ----------------
extern "C" void kernel_launch(void* const* d_in, const int* in_sizes, int n_in,
                              void* d_out, int out_size)
{
    const float* ent    = (const float*)d_in[0];
    const float* fmc_in = (const float*)d_in[1];
    const float* W_fmc  = (const float*)d_in[2];
    const float* b_fmc  = (const float*)d_in[3];
    const float* Bmat   = (const float*)d_in[4];
    const float* Rmat   = (const float*)d_in[5];
    const float* Dmat   = (const float*)d_in[6];
    float* out = (float*)d_out;

    float *pf, *pg, *pfD, *ps, *pmA, *pmB, *pS, *pBt;
    cudaGetSymbolAddress((void**)&pf,  d_f);
    cudaGetSymbolAddress((void**)&pg,  d_g);
    cudaGetSymbolAddress((void**)&pfD, d_fD);
    cudaGetSymbolAddress((void**)&ps,  d_s);
    cudaGetSymbolAddress((void**)&pmA, d_mbarA);
    cudaGetSymbolAddress((void**)&pmB, d_mbarB);
    cudaGetSymbolAddress((void**)&pS,  d_S);
    cudaGetSymbolAddress((void**)&pBt, d_Bt);
    float* S[3] = { pS, pS + M_*C_, pS + 2*M_*C_ };

    // one-time stream/event setup (first call = correctness run, not capture)
    static cudaStream_t s_side = nullptr;
    static cudaEvent_t ev_fork = nullptr, ev_join = nullptr, ev_psi = nullptr;
    if (s_side == nullptr) {
        cudaStreamCreateWithFlags(&s_side, cudaStreamNonBlocking);
        cudaEventCreateWithFlags(&ev_fork, cudaEventDisableTiming);
        cudaEventCreateWithFlags(&ev_join, cudaEventDisableTiming);
        cudaEventCreateWithFlags(&ev_psi,  cudaEventDisableTiming);
        cudaFuncSetAttribute(er_mma,  cudaFuncAttributeMaxDynamicSharedMemorySize, 2 * ER_BUF * 4);
        cudaFuncSetAttribute(phi_mma, cudaFuncAttributeMaxDynamicSharedMemorySize, 2 * PHI_BUF * 4);
    }
    const cudaStream_t mainS = cudaStreamPerThread;

    // fork: side stream runs the front chain concurrently with pack_er + er_mma
    cudaEventRecord(ev_fork, mainS);
    cudaStreamWaitEvent(s_side, ev_fork, 0);

    // ---- side stream: zeros/Bt + f -> tanh -> g+fD -> s -> a ; then psi ----
    pack_front<<<256, 256, 0, s_side>>>(Bmat);
    gemm_nn_ca<<<dim3(5, 2, 15), 256, 0, s_side>>>(fmc_in, W_fmc, nullptr, pf, nullptr,
                                                   100, 300, 900, 64, 15, 0, 0);
    ftanh<<<(M_ * D_ + 255) / 256, 256, 0, s_side>>>(b_fmc);
    gemm_nn_ca<<<dim3(5, 2, 20), 256, 0, s_side>>>(pf, pBt, Dmat, pg, pfD,
                                                   100, 300, 300, 64, 5, 90000, 30000);
    gemm_nt_ca<<<dim3(2, 2, 15), 256, 0, s_side>>>(pfD, pf, ps, 100, 100, 300, 64, 5,
                                                   30000, 10000);
    a_kernel<<<40, 256, 0, s_side>>>();
    cudaEventRecord(ev_join, s_side);            // phi needs only d_a from here
    psi_kernel<<<100, 256, 0, s_side>>>(ent);    // overlaps phi_mma
    cudaEventRecord(ev_psi, s_side);

    // ---- main stream: pack_er -> er_mma ----
    pack_er<<<256, 256, 0, mainS>>>(ent, Rmat);
    er_mma<<<dim3(5, 24, 3), 256, 2 * ER_BUF * 4, mainS>>>();

    // join: phi needs d_a (side) + d_Bpad (main)
    cudaStreamWaitEvent(mainS, ev_join, 0);
    phi_mma<<<dim3(47, 24), 256, 2 * PHI_BUF * 4, mainS>>>();

    // LBP needs psi
    cudaStreamWaitEvent(mainS, ev_psi, 0);
    for (int it = 0; it < 10; it++) {
        const float* msrc = (it & 1) ? pmB : pmA;
        float*       mdst = (it & 1) ? pmA : pmB;
        lbp_fused<<<500, 320, 0, mainS>>>(msrc, mdst,
                                          S[it % 3], S[(it + 1) % 3], S[(it + 2) % 3]);
    }
    final_kernel<<<100, 32, 0, mainS>>>(out, pmA, S[1]);
}

// round 16
// speedup vs baseline: 1.1307x; 1.0278x over previous
#include <cuda_runtime.h>
#include <cuda_fp16.h>
#include <cstdint>
#include <math.h>

#define M_    100
#define C_    30
#define D_    300
#define K_    3
#define MC    3000
#define MM    10000
#define KPAD2 160            // half2 per row (320 fp16, padded from 300)
#define K4    40             // float4 per row (640 B)
#define RPAD  3072           // padded MC rows
#define NPAD  320            // padded rows for R^T (e dim)
#define NCH   10             // chunks of 16 half2 (32 fp16 k-values)

// ---------------- scratch ----------------
static __device__ float    d_f   [M_*D_];
static __device__ float    d_g   [M_*D_];
static __device__ float    d_psi [M_*C_];
static __device__ float    d_fD  [K_*M_*D_];
static __device__ float    d_s   [K_*M_*M_];
static __device__ float    d_a   [M_*M_*K_];
static __device__ uint32_t d_Apad[RPAD*KPAD2];     // ent, fp16x2, padded
static __device__ uint32_t d_Bpad[K_*RPAD*KPAD2];  // ER_k, fp16x2
static __device__ uint32_t d_Rt  [K_*NPAD*KPAD2];  // R_k^T, fp16x2
static __device__ __half   d_phi [MM*C_*C_];       // 18 MB, fp16, [i][j][p][q]
static __device__ float    d_mbarA[M_*M_*C_];
static __device__ float    d_mbarB[M_*M_*C_];
static __device__ float    d_S   [3][M_*C_];       // rotating stot buffers

// ---------------- helpers ----------------
__device__ __forceinline__ uint32_t smem_u32(const void* p) {
    uint32_t a;
    asm("{ .reg .u64 t; cvta.to.shared.u64 t, %1; cvt.u32.u64 %0, t; }" : "=r"(a) : "l"(p));
    return a;
}
__device__ __forceinline__ void cpasync16(uint32_t dst, const void* src) {
    asm volatile("{\n\t.reg .u64 g;\n\tcvta.to.global.u64 g, %1;\n\t"
                 "cp.async.cg.shared.global [%0], [g], 16;\n\t}"
                 :: "r"(dst), "l"(src));
}
__device__ __forceinline__ void cpasync16z(uint32_t dst, const void* src, int bytes) {
    asm volatile("{\n\t.reg .u64 g;\n\tcvta.to.global.u64 g, %1;\n\t"
                 "cp.async.cg.shared.global [%0], [g], 16, %2;\n\t}"
                 :: "r"(dst), "l"(src), "r"(bytes));
}
__device__ __forceinline__ void cpasync4z(uint32_t dst, const void* src, int bytes) {
    asm volatile("{\n\t.reg .u64 g;\n\tcvta.to.global.u64 g, %1;\n\t"
                 "cp.async.ca.shared.global [%0], [g], 4, %2;\n\t}"
                 :: "r"(dst), "l"(src), "r"(bytes));
}
#define CP_COMMIT() asm volatile("cp.async.commit_group;" ::: "memory")
#define CP_WAIT(n)  asm volatile("cp.async.wait_group %0;" :: "n"(n) : "memory")

__device__ __forceinline__ void mma_f16(float* c, const uint32_t* a, const uint32_t* b) {
    asm volatile("mma.sync.aligned.m16n8k16.row.col.f32.f16.f16.f32 "
        "{%0,%1,%2,%3}, {%4,%5,%6,%7}, {%8,%9}, {%0,%1,%2,%3};"
        : "+f"(c[0]), "+f"(c[1]), "+f"(c[2]), "+f"(c[3])
        : "r"(a[0]), "r"(a[1]), "r"(a[2]), "r"(a[3]), "r"(b[0]), "r"(b[1]));
}

// ---------------- pack_front: zeros only (side stream) ----------------------
__global__ void pack_front() {
    int idx = blockIdx.x * blockDim.x + threadIdx.x;
    int stride = gridDim.x * blockDim.x;
    for (int i = idx; i < M_*D_; i += stride) { d_f[i] = 0.f; d_g[i] = 0.f; }
    for (int i = idx; i < K_*M_*D_; i += stride) d_fD[i] = 0.f;
    for (int i = idx; i < K_*MM; i += stride) d_s[i] = 0.f;
    for (int i = idx; i < M_*M_*C_; i += stride) d_mbarA[i] = 0.f;
    for (int i = idx; i < M_*C_; i += stride) { d_S[0][i] = 0.f; d_S[1][i] = 0.f; }
}
// ---------------- pack_er: fp16 Apad + Rt (main stream) ---------------------
__global__ void pack_er(const float* __restrict__ ent, const float* __restrict__ R) {
    int idx = blockIdx.x * blockDim.x + threadIdx.x;
    int stride = gridDim.x * blockDim.x;
    for (int i = idx; i < RPAD*KPAD2; i += stride) {
        int r = i / KPAD2, c2 = i - r * KPAD2;
        int d0 = c2 * 2;
        float x = (r < MC && d0     < D_) ? ent[r * D_ + d0]     : 0.f;
        float y = (r < MC && d0 + 1 < D_) ? ent[r * D_ + d0 + 1] : 0.f;
        half2 h = __floats2half2_rn(x, y);
        d_Apad[i] = *reinterpret_cast<uint32_t*>(&h);
    }
    for (int i = idx; i < K_*NPAD*KPAD2; i += stride) {
        int k = i / (NPAD * KPAD2);
        int rem = i - k * (NPAD * KPAD2);
        int n = rem / KPAD2, c2 = rem - n * KPAD2;
        int d0 = c2 * 2;
        float x = (n < D_ && d0     < D_) ? R[k * D_ * D_ + d0       * D_ + n] : 0.f;
        float y = (n < D_ && d0 + 1 < D_) ? R[k * D_ * D_ + (d0 + 1) * D_ + n] : 0.f;
        half2 h = __floats2half2_rn(x, y);
        d_Rt[i] = *reinterpret_cast<uint32_t*>(&h);
    }
}

// ================= ER via mma.sync fp16 (unchanged) ====================
#define ER_BUF 3840
__global__ void __launch_bounds__(256) er_mma() {
    extern __shared__ uint32_t sm[];
    const int tid = threadIdx.x, lane = tid & 31, wid = tid >> 5;
    const int warpM = wid & 3, warpN = wid >> 2;
    const int row0 = blockIdx.y * 128;
    const int n0   = blockIdx.x * 64;
    const uint32_t smb = smem_u32(sm);
    const float4* Ag = (const float4*)(d_Apad + (size_t)row0 * KPAD2);
    const float4* Bg = (const float4*)(d_Rt + (size_t)blockIdx.z * NPAD * KPAD2
                                       + (size_t)n0 * KPAD2);
    float acc[2][4][4] = {};

    auto prefetch = [&](int ch, int buf) {
        int c4o = ch * 4;
        uint32_t base = smb + buf * ER_BUF * 4;
        #pragma unroll
        for (int it = 0; it < 2; it++) {
            int idx = tid + it * 256;
            int m = idx >> 2, q = idx & 3;
            cpasync16(base + (m * 20 + q * 4) * 4, Ag + m * K4 + c4o + q);
        }
        {
            int n = tid >> 2, q = tid & 3;
            cpasync16(base + (2560 + n * 20 + q * 4) * 4, Bg + n * K4 + c4o + q);
        }
    };

    prefetch(0, 0);
    CP_COMMIT();
    for (int ch = 0; ch < NCH; ch++) {
        if (ch + 1 < NCH) { prefetch(ch + 1, (ch + 1) & 1); CP_COMMIT(); CP_WAIT(1); }
        else CP_WAIT(0);
        __syncthreads();
        const uint32_t* As = sm + (ch & 1) * ER_BUF;
        const uint32_t* Bs = As + 2560;
        #pragma unroll
        for (int ks = 0; ks < 2; ks++) {
            uint32_t af[2][4];
            #pragma unroll
            for (int mf = 0; mf < 2; mf++) {
                int r = warpM * 32 + mf * 16 + (lane >> 2);
                int c = ks * 8 + (lane & 3);
                af[mf][0] = As[r * 20 + c];
                af[mf][1] = As[(r + 8) * 20 + c];
                af[mf][2] = As[r * 20 + c + 4];
                af[mf][3] = As[(r + 8) * 20 + c + 4];
            }
            uint32_t bf[4][2];
            #pragma unroll
            for (int nf = 0; nf < 4; nf++) {
                int n = warpN * 32 + nf * 8 + (lane >> 2);
                int kk = ks * 8 + (lane & 3);
                bf[nf][0] = Bs[n * 20 + kk];
                bf[nf][1] = Bs[n * 20 + kk + 4];
            }
            #pragma unroll
            for (int mf = 0; mf < 2; mf++)
                #pragma unroll
                for (int nf = 0; nf < 4; nf++)
                    mma_f16(acc[mf][nf], af[mf], bf[nf]);
        }
        __syncthreads();
    }

    uint32_t* Bout = d_Bpad + (size_t)blockIdx.z * RPAD * KPAD2;
    #pragma unroll
    for (int mf = 0; mf < 2; mf++) {
        int r = row0 + warpM * 32 + mf * 16 + (lane >> 2);
        #pragma unroll
        for (int nf = 0; nf < 4; nf++) {
            int c = n0 + warpN * 32 + nf * 8 + (lane & 3) * 2;
            half2 h0 = __floats2half2_rn(acc[mf][nf][0], acc[mf][nf][1]);
            half2 h1 = __floats2half2_rn(acc[mf][nf][2], acc[mf][nf][3]);
            Bout[(size_t)r * KPAD2 + (c >> 1)]       = *reinterpret_cast<uint32_t*>(&h0);
            Bout[(size_t)(r + 8) * KPAD2 + (c >> 1)] = *reinterpret_cast<uint32_t*>(&h1);
        }
    }
}

// ===== phi via mma.sync fp16, 3 fused kinds; OUT = fp16 [i][j][p][q] ========
#define PHI_BUF 6400
__global__ void __launch_bounds__(256) phi_mma() {
    extern __shared__ uint32_t sm[];
    const int tid = threadIdx.x, lane = tid & 31, wid = tid >> 5;
    const int warpM = wid & 3, warpN = wid >> 2;
    const int row0 = blockIdx.y * 128;
    const int col0 = blockIdx.x * 64;
    const uint32_t smb = smem_u32(sm);
    const float4* Ag = (const float4*)(d_Apad + (size_t)row0 * KPAD2);
    float acc[3][2][4][4] = {};

    auto prefetch = [&](int ch, int buf) {
        int c4o = ch * 4;
        uint32_t base = smb + buf * PHI_BUF * 4;
        #pragma unroll
        for (int it = 0; it < 2; it++) {
            int idx = tid + it * 256;
            int m = idx >> 2, q = idx & 3;
            cpasync16(base + (m * 20 + q * 4) * 4, Ag + m * K4 + c4o + q);
        }
        #pragma unroll
        for (int it = 0; it < 3; it++) {
            int idx = tid + it * 256;
            int kb = idx >> 8, rem = idx & 255;
            int n = rem >> 2, q = rem & 3;
            const float4* Bg = (const float4*)(d_Bpad + (size_t)kb * RPAD * KPAD2
                                               + (size_t)col0 * KPAD2);
            cpasync16(base + (2560 + kb * 1280 + n * 20 + q * 4) * 4,
                      Bg + n * K4 + c4o + q);
        }
    };

    prefetch(0, 0);
    CP_COMMIT();
    for (int ch = 0; ch < NCH; ch++) {
        if (ch + 1 < NCH) { prefetch(ch + 1, (ch + 1) & 1); CP_COMMIT(); CP_WAIT(1); }
        else CP_WAIT(0);
        __syncthreads();
        const uint32_t* As = sm + (ch & 1) * PHI_BUF;
        #pragma unroll
        for (int ks = 0; ks < 2; ks++) {
            uint32_t af[2][4];
            #pragma unroll
            for (int mf = 0; mf < 2; mf++) {
                int r = warpM * 32 + mf * 16 + (lane >> 2);
                int c = ks * 8 + (lane & 3);
                af[mf][0] = As[r * 20 + c];
                af[mf][1] = As[(r + 8) * 20 + c];
                af[mf][2] = As[r * 20 + c + 4];
                af[mf][3] = As[(r + 8) * 20 + c + 4];
            }
            #pragma unroll
            for (int kb = 0; kb < 3; kb++) {
                const uint32_t* Bs = As + 2560 + kb * 1280;
                uint32_t bf[4][2];
                #pragma unroll
                for (int nf = 0; nf < 4; nf++) {
                    int n = warpN * 32 + nf * 8 + (lane >> 2);
                    int kk = ks * 8 + (lane & 3);
                    bf[nf][0] = Bs[n * 20 + kk];
                    bf[nf][1] = Bs[n * 20 + kk + 4];
                }
                #pragma unroll
                for (int mf = 0; mf < 2; mf++)
                    #pragma unroll
                    for (int nf = 0; nf < 4; nf++)
                        mma_f16(acc[kb][mf][nf], af[mf], bf[nf]);
            }
        }
        __syncthreads();
    }

    #pragma unroll
    for (int mf = 0; mf < 2; mf++) {
        #pragma unroll
        for (int half = 0; half < 2; half++) {
            int r = row0 + warpM * 32 + mf * 16 + (lane >> 2) + half * 8;
            if (r >= MC) continue;
            int i = r / C_, p = r % C_;
            #pragma unroll
            for (int nf = 0; nf < 4; nf++) {
                int c = col0 + warpN * 32 + nf * 8 + (lane & 3) * 2;
                if (c >= MC) continue;
                int j = c / C_, q = c % C_;
                const float* aw = d_a + (i * M_ + j) * 3;
                float w0 = aw[0], w1 = aw[1], w2 = aw[2];
                int e0 = half * 2;
                float v0 = acc[0][mf][nf][e0]     * w0 + acc[1][mf][nf][e0]     * w1
                         + acc[2][mf][nf][e0]     * w2;
                float v1 = acc[0][mf][nf][e0 + 1] * w0 + acc[1][mf][nf][e0 + 1] * w1
                         + acc[2][mf][nf][e0 + 1] * w2;
                half2 hv = __floats2half2_rn(v0, v1);
                *reinterpret_cast<uint32_t*>(
                    d_phi + ((size_t)(i * M_ + j) * (C_ * C_)) + p * C_ + q)
                    = *reinterpret_cast<uint32_t*>(&hv);
            }
        }
    }
}

// ============ cp.async double-buffered split-K fp32 GEMMs ==================
__global__ void __launch_bounds__(256) gemm_nn_ca(
    const float* __restrict__ A, const float* __restrict__ B0,
    const float* __restrict__ B1, float* __restrict__ C0, float* __restrict__ C1,
    int M, int N, int K, int KC, int KS, long sB, long sC)
{
    __shared__ float As[2][64][20];
    __shared__ float Bs[2][16][64];
    const int batch = blockIdx.z / KS, kz = blockIdx.z % KS;
    const float* Bp = (batch == 0) ? B0 : B1 + (long)(batch - 1) * sB;
    float*       Cp = (batch == 0) ? C0 : C1 + (long)(batch - 1) * sC;
    const int tid = threadIdx.x;
    const int row0 = blockIdx.y * 64, col0 = blockIdx.x * 64;
    const int tm = (tid >> 4) * 4, tn = (tid & 15) * 4;
    const int k0 = kz * KC, kend = min(K, k0 + KC);
    if (k0 >= K) return;
    const int S = (kend - k0 + 15) >> 4;
    float acc[4][4] = {};

    auto prefetch = [&](int s, int buf) {
        int kb = k0 + s * 16;
        {
            int m = tid >> 2, q = tid & 3;
            int gr = row0 + m, gc = kb + q * 4;
            int bytes = (gr < M && gc < kend) ? min(16, (kend - gc) * 4) : 0;
            cpasync16z(smem_u32(&As[buf][m][q * 4]), A + (long)gr * K + gc, bytes);
        }
        {
            int kk = tid >> 4, q = tid & 15;
            int gr = kb + kk, gc = col0 + q * 4;
            int bytes = (gr < kend && gc < N) ? min(16, (N - gc) * 4) : 0;
            cpasync16z(smem_u32(&Bs[buf][kk][q * 4]), Bp + (long)gr * N + gc, bytes);
        }
    };

    prefetch(0, 0);
    CP_COMMIT();
    for (int s = 0; s < S; s++) {
        if (s + 1 < S) { prefetch(s + 1, (s + 1) & 1); CP_COMMIT(); CP_WAIT(1); }
        else CP_WAIT(0);
        __syncthreads();
        int buf = s & 1;
        #pragma unroll
        for (int kk = 0; kk < 16; kk++) {
            float a4[4], b4[4];
            #pragma unroll
            for (int x = 0; x < 4; x++) a4[x] = As[buf][tm + x][kk];
            #pragma unroll
            for (int y = 0; y < 4; y++) b4[y] = Bs[buf][kk][tn + y];
            #pragma unroll
            for (int x = 0; x < 4; x++)
                #pragma unroll
                for (int y = 0; y < 4; y++) acc[x][y] += a4[x] * b4[y];
        }
        __syncthreads();
    }
    #pragma unroll
    for (int x = 0; x < 4; x++) {
        int rr = row0 + tm + x;
        if (rr >= M) continue;
        #pragma unroll
        for (int y = 0; y < 4; y++) {
            int cc = col0 + tn + y;
            if (cc >= N) continue;
            atomicAdd(&Cp[(long)rr * N + cc], acc[x][y]);
        }
    }
}

__global__ void __launch_bounds__(256) gemm_nt_ca(
    const float* __restrict__ A, const float* __restrict__ B, float* __restrict__ C,
    int M, int N, int K, int KC, int KS, long sA, long sC)
{
    __shared__ float As[2][64][20];
    __shared__ float Bs[2][16][68];
    const int batch = blockIdx.z / KS, kz = blockIdx.z % KS;
    const float* Ap = A + (long)batch * sA;
    float*       Cp = C + (long)batch * sC;
    const int tid = threadIdx.x;
    const int row0 = blockIdx.y * 64, col0 = blockIdx.x * 64;
    const int tm = (tid >> 4) * 4, tn = (tid & 15) * 4;
    const int k0 = kz * KC, kend = min(K, k0 + KC);
    if (k0 >= K) return;
    const int S = (kend - k0 + 15) >> 4;
    float acc[4][4] = {};

    auto prefetch = [&](int s, int buf) {
        int kb = k0 + s * 16;
        {
            int m = tid >> 2, q = tid & 3;
            int gr = row0 + m, gc = kb + q * 4;
            int bytes = (gr < M && gc < kend) ? min(16, (kend - gc) * 4) : 0;
            cpasync16z(smem_u32(&As[buf][m][q * 4]), Ap + (long)gr * K + gc, bytes);
        }
        #pragma unroll
        for (int it = 0; it < 4; it++) {
            int idx = tid + it * 256;
            int n = idx >> 4, kk = idx & 15;
            int gr = col0 + n, gc = kb + kk;
            int bytes = (gr < N && gc < kend) ? 4 : 0;
            cpasync4z(smem_u32(&Bs[buf][kk][n]), B + (long)gr * K + gc, bytes);
        }
    };

    prefetch(0, 0);
    CP_COMMIT();
    for (int s = 0; s < S; s++) {
        if (s + 1 < S) { prefetch(s + 1, (s + 1) & 1); CP_COMMIT(); CP_WAIT(1); }
        else CP_WAIT(0);
        __syncthreads();
        int buf = s & 1;
        #pragma unroll
        for (int kk = 0; kk < 16; kk++) {
            float a4[4], b4[4];
            #pragma unroll
            for (int x = 0; x < 4; x++) a4[x] = As[buf][tm + x][kk];
            #pragma unroll
            for (int y = 0; y < 4; y++) b4[y] = Bs[buf][kk][tn + y];
            #pragma unroll
            for (int x = 0; x < 4; x++)
                #pragma unroll
                for (int y = 0; y < 4; y++) acc[x][y] += a4[x] * b4[y];
        }
        __syncthreads();
    }
    #pragma unroll
    for (int x = 0; x < 4; x++) {
        int rr = row0 + tm + x;
        if (rr >= M) continue;
        #pragma unroll
        for (int y = 0; y < 4; y++) {
            int cc = col0 + tn + y;
            if (cc >= N) continue;
            atomicAdd(&Cp[(long)rr * N + cc], acc[x][y]);
        }
    }
}

__global__ void ftanh(const float* __restrict__ bias) {
    int idx = blockIdx.x * blockDim.x + threadIdx.x;
    if (idx >= M_ * D_) return;
    d_f[idx] = tanhf(d_f[idx] + bias[idx % D_]);
}

// ---------------- a softmax (needed by phi) ----------------
__global__ void a_kernel()
{
    int ij = blockIdx.x * blockDim.x + threadIdx.x;
    if (ij >= MM) return;
    const float scale = 0.05773502691896258f;
    float s0 = d_s[0 * MM + ij] * scale;
    float s1 = d_s[1 * MM + ij] * scale;
    float s2 = d_s[2 * MM + ij] * scale;
    float mx = fmaxf(s0, fmaxf(s1, s2));
    float e0 = expf(s0 - mx), e1 = expf(s1 - mx), e2 = expf(s2 - mx);
    float inv = 1.f / (e0 + e1 + e2);
    d_a[ij * 3 + 0] = e0 * inv;
    d_a[ij * 3 + 1] = e1 * inv;
    d_a[ij * 3 + 2] = e2 * inv;
}

// ---------------- psi (needed only by LBP; overlaps phi) ----------------
__global__ void psi_kernel(const float* __restrict__ ent)
{
    int m = blockIdx.x;
    __shared__ float gs[D_];
    for (int d = threadIdx.x; d < D_; d += blockDim.x) gs[d] = d_g[m * D_ + d];
    __syncthreads();
    int w = threadIdx.x >> 5, lane = threadIdx.x & 31;
    for (int c = w; c < C_; c += (blockDim.x >> 5)) {
        const float* e = ent + ((long)m * C_ + c) * D_;
        float s = 0.f;
        for (int d = lane; d < D_; d += 32) s += e[d] * gs[d];
        #pragma unroll
        for (int o = 16; o; o >>= 1) s += __shfl_down_sync(0xffffffffu, s, o);
        if (lane == 0) d_psi[m * C_ + c] = s;
    }
}

// ---------------- fused LBP iteration (R11 scalar version) ----------------
__global__ void __launch_bounds__(320) lbp_fused(
    const float* __restrict__ mb_src, float* __restrict__ mb_dst,
    const float* __restrict__ stot_src, float* __restrict__ stot_dst,
    float* __restrict__ stot_zero)
{
    const int tid = threadIdx.x;
    const int w = tid >> 5, lane = tid & 31;
    const int b = blockIdx.x;
    const int j = b % M_;
    const int i = (b / M_) * 10 + w;
    __shared__ float tt[10][32];
    __shared__ float sred[10][32];

    if (b < 12) {
        int z = b * 320 + tid;
        if (z < M_ * C_) stot_zero[z] = 0.f;
    }

    if (lane < C_)
        tt[w][lane] = d_psi[i * C_ + lane] + stot_src[i * C_ + lane]
                    - mb_src[(j * M_ + i) * C_ + lane];
    __syncwarp();

    const __half* ph = d_phi + (size_t)(i * M_ + j) * (C_ * C_);
    float mv = -1e30f;
    if (lane < C_) {
        #pragma unroll 6
        for (int p = 0; p < C_; p++)
            mv = fmaxf(mv, tt[w][p] + __half2float(ph[p * C_ + lane]));
        mv = fmaxf(mv, 0.f);
    }
    float mx = (lane < C_) ? mv : -1e30f;
    #pragma unroll
    for (int o = 16; o; o >>= 1) mx = fmaxf(mx, __shfl_xor_sync(0xffffffffu, mx, o));
    float e = (lane < C_) ? __expf(mv - mx) : 0.f;
    float sum = e;
    #pragma unroll
    for (int o = 16; o; o >>= 1) sum += __shfl_xor_sync(0xffffffffu, sum, o);

    float newm = 0.f;
    if (lane < C_) {
        float sm = e / sum;
        float old = mb_src[(i * M_ + j) * C_ + lane];
        newm = __logf(0.5f * __expf(old) + 0.5f * sm);
        mb_dst[(i * M_ + j) * C_ + lane] = newm;
    }
    sred[w][lane] = newm;
    __syncthreads();

    if (tid < C_) {
        float s = 0.f;
        #pragma unroll
        for (int w2 = 0; w2 < 10; w2++) s += sred[w2][tid];
        atomicAdd(&stot_dst[j * C_ + tid], s);
    }
}

__global__ void final_kernel(float* __restrict__ out, const float* __restrict__ mbar,
                             const float* __restrict__ stot)
{
    int i = blockIdx.x;
    int lane = threadIdx.x;
    float u = -1e30f;
    if (lane < C_)
        u = d_psi[i * C_ + lane] + stot[i * C_ + lane]
          - mbar[(i * M_ + i) * C_ + lane];
    float mx = u;
    #pragma unroll
    for (int o = 16; o; o >>= 1) mx = fmaxf(mx, __shfl_xor_sync(0xffffffffu, mx, o));
    float e = (lane < C_) ? expf(u - mx) : 0.f;
    float sum = e;
    #pragma unroll
    for (int o = 16; o; o >>= 1) sum += __shfl_xor_sync(0xffffffffu, sum, o);
    if (lane < C_) out[i * C_ + lane] = e / sum;
}

// ---------------- host ----------------
extern "C" void kernel_launch(void* const* d_in, const int* in_sizes, int n_in,
                              void* d_out, int out_size)
{
    const float* ent    = (const float*)d_in[0];
    const float* fmc_in = (const float*)d_in[1];
    const float* W_fmc  = (const float*)d_in[2];
    const float* b_fmc  = (const float*)d_in[3];
    const float* Bmat   = (const float*)d_in[4];
    const float* Rmat   = (const float*)d_in[5];
    const float* Dmat   = (const float*)d_in[6];
    float* out = (float*)d_out;

    float *pf, *pg, *pfD, *ps, *pmA, *pmB, *pS;
    cudaGetSymbolAddress((void**)&pf,  d_f);
    cudaGetSymbolAddress((void**)&pg,  d_g);
    cudaGetSymbolAddress((void**)&pfD, d_fD);
    cudaGetSymbolAddress((void**)&ps,  d_s);
    cudaGetSymbolAddress((void**)&pmA, d_mbarA);
    cudaGetSymbolAddress((void**)&pmB, d_mbarB);
    cudaGetSymbolAddress((void**)&pS,  d_S);
    float* S[3] = { pS, pS + M_*C_, pS + 2*M_*C_ };

    // one-time stream/event setup (first call = correctness run, not capture)
    static cudaStream_t s_side = nullptr;
    static cudaEvent_t ev_fork = nullptr, ev_join = nullptr, ev_psi = nullptr;
    if (s_side == nullptr) {
        cudaStreamCreateWithFlags(&s_side, cudaStreamNonBlocking);
        cudaEventCreateWithFlags(&ev_fork, cudaEventDisableTiming);
        cudaEventCreateWithFlags(&ev_join, cudaEventDisableTiming);
        cudaEventCreateWithFlags(&ev_psi,  cudaEventDisableTiming);
        cudaFuncSetAttribute(er_mma,  cudaFuncAttributeMaxDynamicSharedMemorySize, 2 * ER_BUF * 4);
        cudaFuncSetAttribute(phi_mma, cudaFuncAttributeMaxDynamicSharedMemorySize, 2 * PHI_BUF * 4);
    }
    const cudaStream_t mainS = cudaStreamPerThread;

    // fork: side stream runs the front chain concurrently with pack_er + er_mma
    cudaEventRecord(ev_fork, mainS);
    cudaStreamWaitEvent(s_side, ev_fork, 0);

    // ---- side stream (critical): zeros -> f -> tanh -> fD -> s -> a ----
    pack_front<<<256, 256, 0, s_side>>>();
    // f = fmc_in @ W_fmc: split-K 19 (KC=48, 3-stage chains)
    gemm_nn_ca<<<dim3(5, 2, 19), 256, 0, s_side>>>(fmc_in, W_fmc, nullptr, pf, nullptr,
                                                   100, 300, 900, 48, 19, 0, 0);
    ftanh<<<(M_ * D_ + 255) / 256, 256, 0, s_side>>>(b_fmc);
    // fD_k = f @ D_k: 3 batches x split-K 7 (KC=48)
    gemm_nn_ca<<<dim3(5, 2, 21), 256, 0, s_side>>>(pf, Dmat, Dmat + 90000, pfD, pfD + 30000,
                                                   100, 300, 300, 48, 7, 90000, 30000);
    // s_k = fD_k @ f^T: 3 batches x split-K 7
    gemm_nt_ca<<<dim3(2, 2, 21), 256, 0, s_side>>>(pfD, pf, ps, 100, 100, 300, 48, 7,
                                                   30000, 10000);
    a_kernel<<<40, 256, 0, s_side>>>();
    cudaEventRecord(ev_join, s_side);            // phi needs only d_a from here
    // ---- off-critical (overlaps phi): g = f @ B^T (NT vs Bmat), then psi ----
    gemm_nt_ca<<<dim3(5, 2, 7), 256, 0, s_side>>>(pf, Bmat, pg, 100, 300, 300, 48, 7,
                                                  0, 0);
    psi_kernel<<<100, 256, 0, s_side>>>(ent);
    cudaEventRecord(ev_psi, s_side);

    // ---- main stream: pack_er -> er_mma ----
    pack_er<<<256, 256, 0, mainS>>>(ent, Rmat);
    er_mma<<<dim3(5, 24, 3), 256, 2 * ER_BUF * 4, mainS>>>();

    // join: phi needs d_a (side) + d_Bpad (main)
    cudaStreamWaitEvent(mainS, ev_join, 0);
    phi_mma<<<dim3(47, 24), 256, 2 * PHI_BUF * 4, mainS>>>();

    // LBP needs psi
    cudaStreamWaitEvent(mainS, ev_psi, 0);
    for (int it = 0; it < 10; it++) {
        const float* msrc = (it & 1) ? pmB : pmA;
        float*       mdst = (it & 1) ? pmA : pmB;
        lbp_fused<<<1000, 320, 0, mainS>>>(msrc, mdst,
                                           S[it % 3], S[(it + 1) % 3], S[(it + 2) % 3]);
    }
    final_kernel<<<100, 32, 0, mainS>>>(out, pmA, S[1]);
}